// round 1
// baseline (speedup 1.0000x reference)
#include <cuda_runtime.h>
#include <cuda_bf16.h>
#include <math.h>

// Problem constants
#define Nn 50000
#define Ee 800000
#define Gg 512

// ---------------- scratch (device globals; no allocation allowed) ----------------
__device__ __align__(256) float g_H[Nn * 256];     // x@W per layer (pre-aggregation features)
__device__ __align__(256) float g_R[Nn * 256];     // residual projection
__device__ __align__(256) float g_Agg[Nn * 256];   // aggregated GAT output
__device__ __align__(256) float g_X1[Nn * 256];    // layer1 output
__device__ __align__(256) float g_X2[Nn * 128];    // layer2 output
__device__ __align__(256) float g_X3[Nn * 128];    // layer3 output
__device__ __align__(256) float g_asrc[Nn * 8];
__device__ __align__(256) float g_adst[Nn * 8];
__device__ __align__(256) unsigned g_emax[Nn * 8]; // order-encoded float max
__device__ __align__(256) float g_denom[Nn * 8];
__device__ __align__(256) float g_cnt[Gg];

// ---------------- helpers ----------------
__device__ __forceinline__ float lrelu(float x) { return x > 0.0f ? x : 0.2f * x; }

// order-preserving float <-> uint encoding for atomicMax on floats (incl. negatives)
__device__ __forceinline__ unsigned fenc(float f) {
    unsigned u = __float_as_uint(f);
    return (u & 0x80000000u) ? ~u : (u | 0x80000000u);
}
__device__ __forceinline__ float fdec(unsigned e) {
    return (e & 0x80000000u) ? __uint_as_float(e & 0x7FFFFFFFu) : __uint_as_float(~e);
}

__device__ __forceinline__ void red4(float* p, float4 v) {
    // sm_90+: unused-return atomicAdd(float4) lowers to RED.E.ADD.V4 (no return trip)
    atomicAdd(reinterpret_cast<float4*>(p), v);
}

// ---------------- GEMM: C[M,Nout] = A[M,K] @ B[K,Nout] (+ bias) ----------------
// 64x64 tile, 256 threads, 4x4 micro-tile, K-tile 16. K % 16 == 0, Nout % 64 == 0.
__global__ void k_gemm(const float* __restrict__ A, const float* __restrict__ B,
                       const float* __restrict__ bias, float* __restrict__ C,
                       int M, int K, int Nout) {
    __shared__ float As[16][68];
    __shared__ float Bs[16][68];
    const int tx = threadIdx.x & 15;
    const int ty = threadIdx.x >> 4;
    const int row0 = blockIdx.y * 64;
    const int col0 = blockIdx.x * 64;

    float acc[4][4] = {};

    const int ra = threadIdx.x >> 2;        // 0..63 (A tile row)
    const int ka = (threadIdx.x & 3) * 4;   // 0,4,8,12
    const int kb = threadIdx.x >> 4;        // 0..15 (B tile k)
    const int cb = (threadIdx.x & 15) * 4;  // 0..60

    for (int k0 = 0; k0 < K; k0 += 16) {
        float4 av = make_float4(0.f, 0.f, 0.f, 0.f);
        if (row0 + ra < M)
            av = *reinterpret_cast<const float4*>(&A[(size_t)(row0 + ra) * K + k0 + ka]);
        As[ka + 0][ra] = av.x; As[ka + 1][ra] = av.y;
        As[ka + 2][ra] = av.z; As[ka + 3][ra] = av.w;

        float4 bv = *reinterpret_cast<const float4*>(&B[(size_t)(k0 + kb) * Nout + col0 + cb]);
        Bs[kb][cb + 0] = bv.x; Bs[kb][cb + 1] = bv.y;
        Bs[kb][cb + 2] = bv.z; Bs[kb][cb + 3] = bv.w;
        __syncthreads();

#pragma unroll
        for (int k = 0; k < 16; k++) {
            float a_[4], b_[4];
#pragma unroll
            for (int i = 0; i < 4; i++) a_[i] = As[k][ty * 4 + i];
#pragma unroll
            for (int j = 0; j < 4; j++) b_[j] = Bs[k][tx * 4 + j];
#pragma unroll
            for (int i = 0; i < 4; i++)
#pragma unroll
                for (int j = 0; j < 4; j++)
                    acc[i][j] = fmaf(a_[i], b_[j], acc[i][j]);
        }
        __syncthreads();
    }

#pragma unroll
    for (int i = 0; i < 4; i++) {
        int row = row0 + ty * 4 + i;
        if (row >= M) continue;
#pragma unroll
        for (int j = 0; j < 4; j++) {
            int col = col0 + tx * 4 + j;
            float c = acc[i][j];
            if (bias) c += bias[col];
            C[(size_t)row * Nout + col] = c;
        }
    }
}

// ---------------- per-node attention scores + self-loop max init ----------------
__global__ void k_scores(const float* __restrict__ H, const float* __restrict__ a_s,
                         const float* __restrict__ a_d, int Hh, int C) {
    int idx = blockIdx.x * blockDim.x + threadIdx.x;
    if (idx >= Nn * Hh) return;
    int n = idx / Hh, h = idx - n * Hh;
    int D = Hh * C;
    const float* hp = H + (size_t)n * D + h * C;
    float as = 0.f, ad = 0.f;
    for (int c = 0; c < C; c++) {
        float v = hp[c];
        as = fmaf(v, a_s[h * C + c], as);
        ad = fmaf(v, a_d[h * C + c], ad);
    }
    g_asrc[idx] = as;
    g_adst[idx] = ad;
    g_emax[idx] = fenc(lrelu(as + ad));   // self-loop edge
}

// ---------------- edge max (segment max over dst) ----------------
__global__ void k_edge_max(const int* __restrict__ ei, int Hh) {
    int idx = blockIdx.x * blockDim.x + threadIdx.x;
    if (idx >= Ee * Hh) return;
    int e = idx / Hh, h = idx - e * Hh;
    int s = ei[e], d = ei[Ee + e];
    float ev = lrelu(g_asrc[s * Hh + h] + g_adst[d * Hh + h]);
    atomicMax(&g_emax[d * Hh + h], fenc(ev));
}

// ---------------- denominator init (self loop) ----------------
__global__ void k_dinit(int Hh) {
    int idx = blockIdx.x * blockDim.x + threadIdx.x;
    if (idx >= Nn * Hh) return;
    float es = lrelu(g_asrc[idx] + g_adst[idx]);
    g_denom[idx] = __expf(es - fdec(g_emax[idx])) ;
}

__global__ void k_edge_den(const int* __restrict__ ei, int Hh) {
    int idx = blockIdx.x * blockDim.x + threadIdx.x;
    if (idx >= Ee * Hh) return;
    int e = idx / Hh, h = idx - e * Hh;
    int s = ei[e], d = ei[Ee + e];
    float ev = lrelu(g_asrc[s * Hh + h] + g_adst[d * Hh + h]);
    atomicAdd(&g_denom[d * Hh + h], __expf(ev - fdec(g_emax[d * Hh + h])));
}

// ---------------- aggregation init with self-loop message ----------------
__global__ void k_agg_init(int Hh, int C) {
    int nf4 = Hh * C / 4;
    int idx = blockIdx.x * blockDim.x + threadIdx.x;
    if (idx >= Nn * nf4) return;
    int n = idx / nf4, j = idx - n * nf4;
    int h = (j * 4) / C;
    float m = fdec(g_emax[n * Hh + h]);
    float den = g_denom[n * Hh + h] + 1e-16f;
    float es = lrelu(g_asrc[n * Hh + h] + g_adst[n * Hh + h]);
    float alpha = __expf(es - m) / den;
    float4 hv = reinterpret_cast<const float4*>(g_H)[idx];
    float4 o = make_float4(hv.x * alpha, hv.y * alpha, hv.z * alpha, hv.w * alpha);
    reinterpret_cast<float4*>(g_Agg)[idx] = o;
}

// ---------------- edge aggregation: warp per edge, float4 RED ----------------
__global__ void k_edge_agg(const int* __restrict__ ei, int Hh, int C) {
    int w = (blockIdx.x * blockDim.x + threadIdx.x) >> 5;
    if (w >= Ee) return;
    int lane = threadIdx.x & 31;
    int s = ei[w], d = ei[Ee + w];
    int nf4 = Hh * C / 4;
    int cdiv = C / 4;

    float wv = 0.f;
    if (lane < Hh) {
        float ev = lrelu(g_asrc[s * Hh + lane] + g_adst[d * Hh + lane]);
        float m = fdec(g_emax[d * Hh + lane]);
        wv = __expf(ev - m) / (g_denom[d * Hh + lane] + 1e-16f);
    }

    for (int j = lane; j < nf4; j += 32) {
        int h = j / cdiv;
        float wj = __shfl_sync(0xFFFFFFFFu, wv, h);
        float4 hv = reinterpret_cast<const float4*>(g_H)[(size_t)s * nf4 + j];
        float4 v = make_float4(hv.x * wj, hv.y * wj, hv.z * wj, hv.w * wj);
        red4(&g_Agg[((size_t)d * nf4 + j) * 4], v);
    }
}

// ---------------- LayerNorm + residual + ELU: warp per node ----------------
__global__ void k_post(const float* __restrict__ bias, const float* __restrict__ gam,
                       const float* __restrict__ bet, float* __restrict__ Xout, int D) {
    int n = (blockIdx.x * blockDim.x + threadIdx.x) >> 5;
    if (n >= Nn) return;
    int lane = threadIdx.x & 31;
    int nIt = D >> 5;                    // 8 (D=256) or 4 (D=128)
    float vals[8];
    float s = 0.f, s2 = 0.f;
    for (int t = 0; t < nIt; t++) {
        int k = lane + t * 32;
        float v = g_Agg[(size_t)n * D + k] + bias[k];
        vals[t] = v;
        s += v;
        s2 = fmaf(v, v, s2);
    }
#pragma unroll
    for (int o = 16; o > 0; o >>= 1) {
        s  += __shfl_xor_sync(0xFFFFFFFFu, s,  o);
        s2 += __shfl_xor_sync(0xFFFFFFFFu, s2, o);
    }
    float mean = s / (float)D;
    float var = s2 / (float)D - mean * mean;
    float inv = rsqrtf(var + 1e-5f);
    for (int t = 0; t < nIt; t++) {
        int k = lane + t * 32;
        float xn = (vals[t] - mean) * inv * gam[k] + bet[k] + g_R[(size_t)n * D + k];
        Xout[(size_t)n * D + k] = xn > 0.f ? xn : expm1f(xn);
    }
}

// ---------------- pooling ----------------
__global__ void k_pool_zero(float* __restrict__ out) {
    int idx = blockIdx.x * blockDim.x + threadIdx.x;
    if (idx < Gg * 128) out[idx] = 0.f;
    if (idx < Gg) g_cnt[idx] = 0.f;
}

__global__ void k_pool(const int* __restrict__ batch, float* __restrict__ out) {
    int idx = blockIdx.x * blockDim.x + threadIdx.x;
    if (idx >= Nn * 32) return;
    int n = idx >> 5, j = idx & 31;
    int b = batch[n];
    float4 v = reinterpret_cast<const float4*>(g_X3)[n * 32 + j];
    red4(&out[b * 128 + j * 4], v);
    if (j == 0) atomicAdd(&g_cnt[b], 1.0f);
}

__global__ void k_pool_div(float* __restrict__ out) {
    int idx = blockIdx.x * blockDim.x + threadIdx.x;
    if (idx >= Gg * 128) return;
    out[idx] /= fmaxf(g_cnt[idx >> 7], 1.0f);
}

// ---------------- host orchestration ----------------
static void run_layer(const float* Xin, const int* ei,
                      const float* W, const float* asv, const float* adv,
                      const float* bb, const float* gg, const float* bbe,
                      const float* pw, const float* pb,
                      float* pH, float* pR, float* Xout,
                      int Kin, int Hh, int C) {
    const int D = Hh * C;
    const int TB = 256;
    dim3 gH(D / 64, (Nn + 63) / 64);
    k_gemm<<<gH, TB>>>(Xin, W, nullptr, pH, Nn, Kin, D);
    k_gemm<<<gH, TB>>>(Xin, pw, pb, pR, Nn, Kin, D);
    k_scores<<<(Nn * Hh + TB - 1) / TB, TB>>>(pH, asv, adv, Hh, C);
    k_edge_max<<<(Ee * Hh + TB - 1) / TB, TB>>>(ei, Hh);
    k_dinit<<<(Nn * Hh + TB - 1) / TB, TB>>>(Hh);
    k_edge_den<<<(Ee * Hh + TB - 1) / TB, TB>>>(ei, Hh);
    int nf4 = D / 4;
    k_agg_init<<<(Nn * nf4 + TB - 1) / TB, TB>>>(Hh, C);
    k_edge_agg<<<((size_t)Ee * 32 + TB - 1) / TB, TB>>>(ei, Hh, C);
    k_post<<<((size_t)Nn * 32 + TB - 1) / TB, TB>>>(bb, gg, bbe, Xout, D);
}

extern "C" void kernel_launch(void* const* d_in, const int* in_sizes, int n_in,
                              void* d_out, int out_size) {
    const float* x   = (const float*)d_in[0];
    const int* ei    = (const int*)d_in[1];
    const int* batch = (const int*)d_in[2];
    const float* W1 = (const float*)d_in[3],  *as1 = (const float*)d_in[4],
               *ad1 = (const float*)d_in[5],  *b1  = (const float*)d_in[6],
               *g1  = (const float*)d_in[7],  *be1 = (const float*)d_in[8],
               *pw1 = (const float*)d_in[9],  *pb1 = (const float*)d_in[10];
    const float* W2 = (const float*)d_in[11], *as2 = (const float*)d_in[12],
               *ad2 = (const float*)d_in[13], *b2  = (const float*)d_in[14],
               *g2  = (const float*)d_in[15], *be2 = (const float*)d_in[16],
               *pw2 = (const float*)d_in[17], *pb2 = (const float*)d_in[18];
    const float* W3 = (const float*)d_in[19], *as3 = (const float*)d_in[20],
               *ad3 = (const float*)d_in[21], *b3  = (const float*)d_in[22],
               *g3  = (const float*)d_in[23], *be3 = (const float*)d_in[24],
               *pw3 = (const float*)d_in[25], *pb3 = (const float*)d_in[26];
    float* out = (float*)d_out;

    void *pH_, *pR_, *pX1_, *pX2_, *pX3_;
    cudaGetSymbolAddress(&pH_,  g_H);
    cudaGetSymbolAddress(&pR_,  g_R);
    cudaGetSymbolAddress(&pX1_, g_X1);
    cudaGetSymbolAddress(&pX2_, g_X2);
    cudaGetSymbolAddress(&pX3_, g_X3);
    float* pH  = (float*)pH_;
    float* pR  = (float*)pR_;
    float* pX1 = (float*)pX1_;
    float* pX2 = (float*)pX2_;
    float* pX3 = (float*)pX3_;

    // Layer 1: 128 -> 8 heads x 32 (concat -> 256)
    run_layer(x,   ei, W1, as1, ad1, b1, g1, be1, pw1, pb1, pH, pR, pX1, 128, 8, 32);
    // Layer 2: 256 -> 4 heads x 32 (concat -> 128)
    run_layer(pX1, ei, W2, as2, ad2, b2, g2, be2, pw2, pb2, pH, pR, pX2, 256, 4, 32);
    // Layer 3: 128 -> 1 head x 128 (mean over 1 head == identity)
    run_layer(pX2, ei, W3, as3, ad3, b3, g3, be3, pw3, pb3, pH, pR, pX3, 128, 1, 128);

    const int TB = 256;
    k_pool_zero<<<(Gg * 128 + TB - 1) / TB, TB>>>(out);
    k_pool<<<((size_t)Nn * 32 + TB - 1) / TB, TB>>>(batch, out);
    k_pool_div<<<(Gg * 128 + TB - 1) / TB, TB>>>(out);
}

// round 2
// speedup vs baseline: 1.4647x; 1.4647x over previous
#include <cuda_runtime.h>
#include <cuda_bf16.h>
#include <math.h>

#define Nn 50000
#define Ee 800000
#define Gg 512
#define NSCAN_BLK 196          // ceil(50000/256)

// ---------------- scratch ----------------
__device__ __align__(256) float g_H[Nn * 256];
__device__ __align__(256) float g_R[Nn * 256];
__device__ __align__(256) float g_X1[Nn * 256];
__device__ __align__(256) float g_X2[Nn * 128];
__device__ __align__(256) float g_X3[Nn * 128];
__device__ __align__(256) float g_asrc[Nn * 8];
__device__ __align__(256) float g_adst[Nn * 8];
__device__ __align__(256) float g_cnt[Gg];
// CSR
__device__ int g_deg[Nn];
__device__ int g_off[Nn];
__device__ int g_cur[Nn];
__device__ int g_srcs[Ee];
__device__ int g_bsum[256];

__device__ __forceinline__ float lrelu(float x) { return x > 0.0f ? x : 0.2f * x; }

__device__ __forceinline__ void red4(float* p, float4 v) {
    atomicAdd(reinterpret_cast<float4*>(p), v);
}

// =========================== CSR build ===========================
__global__ void k_zero_deg() {
    int i = blockIdx.x * blockDim.x + threadIdx.x;
    if (i < Nn) g_deg[i] = 0;
}
__global__ void k_hist(const int* __restrict__ ei) {
    int e = blockIdx.x * blockDim.x + threadIdx.x;
    if (e < Ee) atomicAdd(&g_deg[ei[Ee + e]], 1);
}
__global__ void k_scan1() {          // 196 blocks x 256
    __shared__ int sh[256];
    int tid = threadIdx.x;
    int i = blockIdx.x * 256 + tid;
    int v = (i < Nn) ? g_deg[i] : 0;
    sh[tid] = v; __syncthreads();
    for (int off = 1; off < 256; off <<= 1) {
        int t = (tid >= off) ? sh[tid - off] : 0;
        __syncthreads();
        sh[tid] += t;
        __syncthreads();
    }
    if (i < Nn) g_off[i] = sh[tid] - v;          // exclusive within block
    if (tid == 255) g_bsum[blockIdx.x] = sh[255];
}
__global__ void k_scan2() {          // 1 block x 256
    __shared__ int sh[256];
    int tid = threadIdx.x;
    int v = (tid < NSCAN_BLK) ? g_bsum[tid] : 0;
    sh[tid] = v; __syncthreads();
    for (int off = 1; off < 256; off <<= 1) {
        int t = (tid >= off) ? sh[tid - off] : 0;
        __syncthreads();
        sh[tid] += t;
        __syncthreads();
    }
    if (tid < NSCAN_BLK) g_bsum[tid] = sh[tid] - v;  // exclusive
}
__global__ void k_scan3() {
    int i = blockIdx.x * blockDim.x + threadIdx.x;
    if (i < Nn) {
        g_off[i] += g_bsum[i >> 8];
        g_cur[i] = 0;
    }
}
__global__ void k_scatter(const int* __restrict__ ei) {
    int e = blockIdx.x * blockDim.x + threadIdx.x;
    if (e >= Ee) return;
    int d = ei[Ee + e];
    int pos = g_off[d] + atomicAdd(&g_cur[d], 1);
    g_srcs[pos] = ei[e];
}

// =========================== GEMM ===========================
// C[M,Nout] = A[M,K] @ B[K,Nout] (+bias). 128x128 tile, 256 thr, 8x8 micro, Ktile 8.
__global__ __launch_bounds__(256) void k_gemm(
        const float* __restrict__ A, const float* __restrict__ B,
        const float* __restrict__ bias, float* __restrict__ C,
        int M, int K, int Nout) {
    __shared__ float As[8][132];
    __shared__ float Bs[8][132];
    const int tid = threadIdx.x;
    const int tx = tid & 15;
    const int ty = tid >> 4;
    const int row0 = blockIdx.y * 128;
    const int col0 = blockIdx.x * 128;

    const int ar = tid >> 1;            // 0..127
    const int ak = (tid & 1) * 4;       // 0 or 4
    const int bk = tid >> 5;            // 0..7
    const int bc = (tid & 31) * 4;      // 0..124

    float acc[8][8] = {};

    for (int k0 = 0; k0 < K; k0 += 8) {
        float4 av = make_float4(0.f, 0.f, 0.f, 0.f);
        if (row0 + ar < M)
            av = *reinterpret_cast<const float4*>(&A[(size_t)(row0 + ar) * K + k0 + ak]);
        As[ak + 0][ar] = av.x; As[ak + 1][ar] = av.y;
        As[ak + 2][ar] = av.z; As[ak + 3][ar] = av.w;

        float4 bv = *reinterpret_cast<const float4*>(&B[(size_t)(k0 + bk) * Nout + col0 + bc]);
        *reinterpret_cast<float4*>(&Bs[bk][bc]) = bv;
        __syncthreads();

#pragma unroll
        for (int k = 0; k < 8; k++) {
            float4 a0 = *reinterpret_cast<const float4*>(&As[k][ty * 8]);
            float4 a1 = *reinterpret_cast<const float4*>(&As[k][ty * 8 + 4]);
            float4 b0 = *reinterpret_cast<const float4*>(&Bs[k][tx * 8]);
            float4 b1 = *reinterpret_cast<const float4*>(&Bs[k][tx * 8 + 4]);
            float a_[8] = {a0.x, a0.y, a0.z, a0.w, a1.x, a1.y, a1.z, a1.w};
            float b_[8] = {b0.x, b0.y, b0.z, b0.w, b1.x, b1.y, b1.z, b1.w};
#pragma unroll
            for (int i = 0; i < 8; i++)
#pragma unroll
                for (int j = 0; j < 8; j++)
                    acc[i][j] = fmaf(a_[i], b_[j], acc[i][j]);
        }
        __syncthreads();
    }

    float bj[8];
#pragma unroll
    for (int j = 0; j < 8; j++) bj[j] = bias ? bias[col0 + tx * 8 + j] : 0.f;

#pragma unroll
    for (int i = 0; i < 8; i++) {
        int row = row0 + ty * 8 + i;
        if (row >= M) continue;
        float4 o0 = make_float4(acc[i][0] + bj[0], acc[i][1] + bj[1],
                                acc[i][2] + bj[2], acc[i][3] + bj[3]);
        float4 o1 = make_float4(acc[i][4] + bj[4], acc[i][5] + bj[5],
                                acc[i][6] + bj[6], acc[i][7] + bj[7]);
        float* cp = &C[(size_t)row * Nout + col0 + tx * 8];
        *reinterpret_cast<float4*>(cp) = o0;
        *reinterpret_cast<float4*>(cp + 4) = o1;
    }
}

// =========================== scores ===========================
__global__ void k_scores(const float* __restrict__ H, const float* __restrict__ a_s,
                         const float* __restrict__ a_d, int Hh, int C) {
    int idx = blockIdx.x * blockDim.x + threadIdx.x;
    if (idx >= Nn * Hh) return;
    int n = idx / Hh, h = idx - n * Hh;
    int D = Hh * C;
    const float4* hp = reinterpret_cast<const float4*>(H + (size_t)n * D + h * C);
    const float4* sp = reinterpret_cast<const float4*>(a_s + h * C);
    const float4* dp = reinterpret_cast<const float4*>(a_d + h * C);
    float as = 0.f, ad = 0.f;
    for (int c = 0; c < C / 4; c++) {
        float4 v = hp[c], s4 = sp[c], d4 = dp[c];
        as = fmaf(v.x, s4.x, fmaf(v.y, s4.y, fmaf(v.z, s4.z, fmaf(v.w, s4.w, as))));
        ad = fmaf(v.x, d4.x, fmaf(v.y, d4.y, fmaf(v.z, d4.z, fmaf(v.w, d4.w, ad))));
    }
    g_asrc[idx] = as;
    g_adst[idx] = ad;
}

// ============ fused GAT gather + softmax + bias + LN + residual + ELU ============
// One warp per destination node. No max-subtraction (scores bounded, exp safe;
// softmax is shift-invariant so result matches reference to fp rounding).
template<int Hh, int C>
__global__ __launch_bounds__(256) void k_gat(
        const float* __restrict__ H, const float* __restrict__ R,
        const float* __restrict__ bias, const float* __restrict__ gam,
        const float* __restrict__ bet, float* __restrict__ Xout) {
    constexpr int D = Hh * C;
    constexpr int NF4 = D / 4;
    constexpr int IT = NF4 / 32;        // 2 for D=256, 1 for D=128
    constexpr int C4 = C / 4;

    int n = blockIdx.x * (blockDim.x >> 5) + (threadIdx.x >> 5);
    if (n >= Nn) return;
    int lane = threadIdx.x & 31;

    float adst_l = (lane < Hh) ? g_adst[n * Hh + lane] : 0.f;
    float denom_l = 0.f;
    float4 acc[IT];
#pragma unroll
    for (int t = 0; t < IT; t++) acc[t] = make_float4(0.f, 0.f, 0.f, 0.f);

    const float4* H4 = reinterpret_cast<const float4*>(H);

    int beg = g_off[n];
    int deg = g_deg[n];
    int s_next = (deg > 0) ? g_srcs[beg] : n;

    for (int e = 0; e <= deg; e++) {
        int s = s_next;
        s_next = (e + 1 < deg) ? g_srcs[beg + e + 1] : n;   // last iter: self-loop
        float w_l = 0.f;
        if (lane < Hh) {
            float ev = lrelu(g_asrc[s * Hh + lane] + adst_l);
            w_l = __expf(ev);
            denom_l += w_l;
        }
#pragma unroll
        for (int t = 0; t < IT; t++) {
            int j = lane + t * 32;
            float wj = __shfl_sync(0xFFFFFFFFu, w_l, j / C4);
            float4 hv = H4[(size_t)s * NF4 + j];
            acc[t].x = fmaf(wj, hv.x, acc[t].x);
            acc[t].y = fmaf(wj, hv.y, acc[t].y);
            acc[t].z = fmaf(wj, hv.z, acc[t].z);
            acc[t].w = fmaf(wj, hv.w, acc[t].w);
        }
    }

    // normalize by softmax denominator
    float vals[IT * 4];
    float s1 = 0.f, s2 = 0.f;
    const float4* B4 = reinterpret_cast<const float4*>(bias);
#pragma unroll
    for (int t = 0; t < IT; t++) {
        int j = lane + t * 32;
        float dj = __shfl_sync(0xFFFFFFFFu, denom_l, j / C4) + 1e-16f;
        float inv = 1.0f / dj;
        float4 bv = B4[j];
        float4 v = make_float4(fmaf(acc[t].x, inv, bv.x), fmaf(acc[t].y, inv, bv.y),
                               fmaf(acc[t].z, inv, bv.z), fmaf(acc[t].w, inv, bv.w));
        vals[t * 4 + 0] = v.x; vals[t * 4 + 1] = v.y;
        vals[t * 4 + 2] = v.z; vals[t * 4 + 3] = v.w;
        s1 += v.x + v.y + v.z + v.w;
        s2 = fmaf(v.x, v.x, fmaf(v.y, v.y, fmaf(v.z, v.z, fmaf(v.w, v.w, s2))));
    }
#pragma unroll
    for (int o = 16; o > 0; o >>= 1) {
        s1 += __shfl_xor_sync(0xFFFFFFFFu, s1, o);
        s2 += __shfl_xor_sync(0xFFFFFFFFu, s2, o);
    }
    float mean = s1 / (float)D;
    float var = s2 / (float)D - mean * mean;
    float inv = rsqrtf(var + 1e-5f);

    const float4* G4 = reinterpret_cast<const float4*>(gam);
    const float4* E4 = reinterpret_cast<const float4*>(bet);
    const float4* R4 = reinterpret_cast<const float4*>(R);
    float4* O4 = reinterpret_cast<float4*>(Xout);
#pragma unroll
    for (int t = 0; t < IT; t++) {
        int j = lane + t * 32;
        float4 gv = G4[j], ev = E4[j], rv = R4[(size_t)n * NF4 + j];
        float x0 = (vals[t * 4 + 0] - mean) * inv * gv.x + ev.x + rv.x;
        float x1 = (vals[t * 4 + 1] - mean) * inv * gv.y + ev.y + rv.y;
        float x2 = (vals[t * 4 + 2] - mean) * inv * gv.z + ev.z + rv.z;
        float x3 = (vals[t * 4 + 3] - mean) * inv * gv.w + ev.w + rv.w;
        float4 o;
        o.x = x0 > 0.f ? x0 : expm1f(x0);
        o.y = x1 > 0.f ? x1 : expm1f(x1);
        o.z = x2 > 0.f ? x2 : expm1f(x2);
        o.w = x3 > 0.f ? x3 : expm1f(x3);
        O4[(size_t)n * NF4 + j] = o;
    }
}

// =========================== pooling ===========================
__global__ void k_pool_zero(float* __restrict__ out) {
    int idx = blockIdx.x * blockDim.x + threadIdx.x;
    if (idx < Gg * 128) out[idx] = 0.f;
    if (idx < Gg) g_cnt[idx] = 0.f;
}
__global__ void k_pool(const int* __restrict__ batch, float* __restrict__ out) {
    int idx = blockIdx.x * blockDim.x + threadIdx.x;
    if (idx >= Nn * 32) return;
    int n = idx >> 5, j = idx & 31;
    int b = batch[n];
    float4 v = reinterpret_cast<const float4*>(g_X3)[n * 32 + j];
    red4(&out[b * 128 + j * 4], v);
    if (j == 0) atomicAdd(&g_cnt[b], 1.0f);
}
__global__ void k_pool_div(float* __restrict__ out) {
    int idx = blockIdx.x * blockDim.x + threadIdx.x;
    if (idx >= Gg * 128) return;
    out[idx] /= fmaxf(g_cnt[idx >> 7], 1.0f);
}

// =========================== host ===========================
extern "C" void kernel_launch(void* const* d_in, const int* in_sizes, int n_in,
                              void* d_out, int out_size) {
    const float* x   = (const float*)d_in[0];
    const int* ei    = (const int*)d_in[1];
    const int* batch = (const int*)d_in[2];
    const float* W1 = (const float*)d_in[3],  *as1 = (const float*)d_in[4],
               *ad1 = (const float*)d_in[5],  *b1  = (const float*)d_in[6],
               *g1  = (const float*)d_in[7],  *be1 = (const float*)d_in[8],
               *pw1 = (const float*)d_in[9],  *pb1 = (const float*)d_in[10];
    const float* W2 = (const float*)d_in[11], *as2 = (const float*)d_in[12],
               *ad2 = (const float*)d_in[13], *b2  = (const float*)d_in[14],
               *g2  = (const float*)d_in[15], *be2 = (const float*)d_in[16],
               *pw2 = (const float*)d_in[17], *pb2 = (const float*)d_in[18];
    const float* W3 = (const float*)d_in[19], *as3 = (const float*)d_in[20],
               *ad3 = (const float*)d_in[21], *b3  = (const float*)d_in[22],
               *g3  = (const float*)d_in[23], *be3 = (const float*)d_in[24],
               *pw3 = (const float*)d_in[25], *pb3 = (const float*)d_in[26];
    float* out = (float*)d_out;

    void *pH_, *pR_, *pX1_, *pX2_, *pX3_;
    cudaGetSymbolAddress(&pH_,  g_H);
    cudaGetSymbolAddress(&pR_,  g_R);
    cudaGetSymbolAddress(&pX1_, g_X1);
    cudaGetSymbolAddress(&pX2_, g_X2);
    cudaGetSymbolAddress(&pX3_, g_X3);
    float* pH  = (float*)pH_;
    float* pR  = (float*)pR_;
    float* pX1 = (float*)pX1_;
    float* pX2 = (float*)pX2_;
    float* pX3 = (float*)pX3_;

    const int TB = 256;

    // ---- CSR build (edge structure shared by all layers) ----
    k_zero_deg<<<(Nn + TB - 1) / TB, TB>>>();
    k_hist<<<(Ee + TB - 1) / TB, TB>>>(ei);
    k_scan1<<<NSCAN_BLK, 256>>>();
    k_scan2<<<1, 256>>>();
    k_scan3<<<(Nn + TB - 1) / TB, TB>>>();
    k_scatter<<<(Ee + TB - 1) / TB, TB>>>(ei);

    // ---- Layer 1: 128 -> 8x32 (D=256) ----
    {
        dim3 g(256 / 128, (Nn + 127) / 128);
        k_gemm<<<g, TB>>>(x, W1, nullptr, pH, Nn, 128, 256);
        k_gemm<<<g, TB>>>(x, pw1, pb1, pR, Nn, 128, 256);
        k_scores<<<(Nn * 8 + TB - 1) / TB, TB>>>(pH, as1, ad1, 8, 32);
        k_gat<8, 32><<<(Nn * 32 + TB - 1) / TB, TB>>>(pH, pR, b1, g1, be1, pX1);
    }
    // ---- Layer 2: 256 -> 4x32 (D=128) ----
    {
        dim3 g(128 / 128, (Nn + 127) / 128);
        k_gemm<<<g, TB>>>(pX1, W2, nullptr, pH, Nn, 256, 128);
        k_gemm<<<g, TB>>>(pX1, pw2, pb2, pR, Nn, 256, 128);
        k_scores<<<(Nn * 4 + TB - 1) / TB, TB>>>(pH, as2, ad2, 4, 32);
        k_gat<4, 32><<<(Nn * 32 + TB - 1) / TB, TB>>>(pH, pR, b2, g2, be2, pX2);
    }
    // ---- Layer 3: 128 -> 1x128 (D=128, mean over 1 head == identity) ----
    {
        dim3 g(128 / 128, (Nn + 127) / 128);
        k_gemm<<<g, TB>>>(pX2, W3, nullptr, pH, Nn, 128, 128);
        k_gemm<<<g, TB>>>(pX2, pw3, pb3, pR, Nn, 128, 128);
        k_scores<<<(Nn * 1 + TB - 1) / TB, TB>>>(pH, as3, ad3, 1, 128);
        k_gat<1, 128><<<(Nn * 32 + TB - 1) / TB, TB>>>(pH, pR, b3, g3, be3, pX3);
    }

    // ---- pooling ----
    k_pool_zero<<<(Gg * 128 + TB - 1) / TB, TB>>>(out);
    k_pool<<<((size_t)Nn * 32 + TB - 1) / TB, TB>>>(batch, out);
    k_pool_div<<<(Gg * 128 + TB - 1) / TB, TB>>>(out);
}

// round 4
// speedup vs baseline: 2.0964x; 1.4313x over previous
#include <cuda_runtime.h>
#include <cuda_bf16.h>
#include <math.h>
#include <stdint.h>

#define Nn 50000
#define Ee 800000
#define Gg 512
#define NSCAN_BLK 196          // ceil(50000/256)

// ---------------- scratch ----------------
__device__ __align__(256) float g_H[Nn * 256];
__device__ __align__(256) float g_R[Nn * 256];
__device__ __align__(256) float g_X1[Nn * 256];
__device__ __align__(256) float g_X2[Nn * 128];
__device__ __align__(256) float g_X3[Nn * 128];
__device__ __align__(256) float g_asrc[Nn * 8];
__device__ __align__(256) float g_adst[Nn * 8];
__device__ __align__(256) float g_cnt[Gg];
// bf16 hi/lo split buffers
__device__ __align__(256) __nv_bfloat16 g_Ahi[Nn * 256];
__device__ __align__(256) __nv_bfloat16 g_Alo[Nn * 256];
__device__ __align__(256) __nv_bfloat16 g_Bhi[512 * 256];
__device__ __align__(256) __nv_bfloat16 g_Blo[512 * 256];
// CSR
__device__ int g_deg[Nn];
__device__ int g_off[Nn];
__device__ int g_cur[Nn];
__device__ int g_srcs[Ee];
__device__ int g_bsum[256];

__device__ __forceinline__ float lrelu(float x) { return x > 0.0f ? x : 0.2f * x; }
__device__ __forceinline__ void red4(float* p, float4 v) {
    atomicAdd(reinterpret_cast<float4*>(p), v);
}

// =========================== CSR build ===========================
__global__ void k_zero_deg() {
    int i = blockIdx.x * blockDim.x + threadIdx.x;
    if (i < Nn) g_deg[i] = 0;
}
__global__ void k_hist(const int* __restrict__ ei) {
    int e = blockIdx.x * blockDim.x + threadIdx.x;
    if (e < Ee) atomicAdd(&g_deg[ei[Ee + e]], 1);
}
__global__ void k_scan1() {
    __shared__ int sh[256];
    int tid = threadIdx.x;
    int i = blockIdx.x * 256 + tid;
    int v = (i < Nn) ? g_deg[i] : 0;
    sh[tid] = v; __syncthreads();
    for (int off = 1; off < 256; off <<= 1) {
        int t = (tid >= off) ? sh[tid - off] : 0;
        __syncthreads();
        sh[tid] += t;
        __syncthreads();
    }
    if (i < Nn) g_off[i] = sh[tid] - v;
    if (tid == 255) g_bsum[blockIdx.x] = sh[255];
}
__global__ void k_scan2() {
    __shared__ int sh[256];
    int tid = threadIdx.x;
    int v = (tid < NSCAN_BLK) ? g_bsum[tid] : 0;
    sh[tid] = v; __syncthreads();
    for (int off = 1; off < 256; off <<= 1) {
        int t = (tid >= off) ? sh[tid - off] : 0;
        __syncthreads();
        sh[tid] += t;
        __syncthreads();
    }
    if (tid < NSCAN_BLK) g_bsum[tid] = sh[tid] - v;
}
__global__ void k_scan3() {
    int i = blockIdx.x * blockDim.x + threadIdx.x;
    if (i < Nn) {
        g_off[i] += g_bsum[i >> 8];
        g_cur[i] = 0;
    }
}
__global__ void k_scatter(const int* __restrict__ ei) {
    int e = blockIdx.x * blockDim.x + threadIdx.x;
    if (e >= Ee) return;
    int d = ei[Ee + e];
    int pos = g_off[d] + atomicAdd(&g_cur[d], 1);
    g_srcs[pos] = ei[e];
}

// =========================== fp32 -> bf16 hi/lo split ===========================
__global__ void k_cvt(const float* __restrict__ X, __nv_bfloat16* __restrict__ hi,
                      __nv_bfloat16* __restrict__ lo, int total4) {
    int i = blockIdx.x * blockDim.x + threadIdx.x;
    if (i >= total4) return;
    float4 v = reinterpret_cast<const float4*>(X)[i];
    __nv_bfloat16 h0 = __float2bfloat16(v.x), h1 = __float2bfloat16(v.y);
    __nv_bfloat16 h2 = __float2bfloat16(v.z), h3 = __float2bfloat16(v.w);
    __nv_bfloat16 l0 = __float2bfloat16(v.x - __bfloat162float(h0));
    __nv_bfloat16 l1 = __float2bfloat16(v.y - __bfloat162float(h1));
    __nv_bfloat16 l2 = __float2bfloat16(v.z - __bfloat162float(h2));
    __nv_bfloat16 l3 = __float2bfloat16(v.w - __bfloat162float(h3));
    __nv_bfloat162* H2 = reinterpret_cast<__nv_bfloat162*>(hi);
    __nv_bfloat162* L2 = reinterpret_cast<__nv_bfloat162*>(lo);
    H2[i * 2]     = __nv_bfloat162(h0, h1);
    H2[i * 2 + 1] = __nv_bfloat162(h2, h3);
    L2[i * 2]     = __nv_bfloat162(l0, l1);
    L2[i * 2 + 1] = __nv_bfloat162(l2, l3);
}

// weights: Bt[n][k] = (n<Dhalf ? W[k][n] : pw[k][n-Dhalf]), split hi/lo
__global__ void k_prepack(const float* __restrict__ W, const float* __restrict__ pw,
                          int K, int Dhalf) {
    int idx = blockIdx.x * blockDim.x + threadIdx.x;
    int Ncat = 2 * Dhalf;
    if (idx >= Ncat * K) return;
    int n = idx / K, k = idx - n * K;
    float w = (n < Dhalf) ? W[(size_t)k * Dhalf + n] : pw[(size_t)k * Dhalf + (n - Dhalf)];
    __nv_bfloat16 h = __float2bfloat16(w);
    g_Bhi[idx] = h;
    g_Blo[idx] = __float2bfloat16(w - __bfloat162float(h));
}

// =========================== HMMA GEMM (mma.sync bf16, 3-pass hi/lo) ===========================
// D[128x128] per CTA = Ahi*Bhi^T + Ahi*Blo^T + Alo*Bhi^T, fp32 accum.
// grid: (Ncat/128, ceil(Nn/128)). First Dhalf cols -> Hout, rest -> Rout (+pb).
#define SROW 40   // padded smem row stride in bf16 elems (80B -> conflict-free frags)
#define KCH 32

__device__ __forceinline__ void mma16816(float* d, const uint32_t* a, const uint32_t* b) {
    asm volatile(
        "mma.sync.aligned.m16n8k16.row.col.f32.bf16.bf16.f32 "
        "{%0,%1,%2,%3}, {%4,%5,%6,%7}, {%8,%9}, {%0,%1,%2,%3};"
        : "+f"(d[0]), "+f"(d[1]), "+f"(d[2]), "+f"(d[3])
        : "r"(a[0]), "r"(a[1]), "r"(a[2]), "r"(a[3]), "r"(b[0]), "r"(b[1]));
}

__global__ __launch_bounds__(256) void k_hgemm(
        const __nv_bfloat16* __restrict__ Ahi, const __nv_bfloat16* __restrict__ Alo,
        const float* __restrict__ pb, float* __restrict__ Hout, float* __restrict__ Rout,
        int K, int Dhalf) {
    __shared__ __nv_bfloat16 sAhi[128 * SROW];
    __shared__ __nv_bfloat16 sAlo[128 * SROW];
    __shared__ __nv_bfloat16 sBhi[128 * SROW];
    __shared__ __nv_bfloat16 sBlo[128 * SROW];

    const int tid = threadIdx.x;
    const int wid = tid >> 5, lane = tid & 31;
    const int row0 = blockIdx.y * 128;
    const int n0 = blockIdx.x * 128;
    const int wr = wid >> 2;      // 0..1 : 64-row block
    const int wc = wid & 3;       // 0..3 : 32-col block
    const int tr = lane >> 2;     // 0..7
    const int tc = (lane & 3) * 2;

    float acc[4][4][4];           // [mi][ni][reg]
#pragma unroll
    for (int mi = 0; mi < 4; mi++)
#pragma unroll
        for (int ni = 0; ni < 4; ni++)
#pragma unroll
            for (int q = 0; q < 4; q++) acc[mi][ni][q] = 0.f;

    for (int kc0 = 0; kc0 < K; kc0 += KCH) {
        // stage 128x32 tiles of Ahi/Alo/Bhi/Blo (each 512 uint4 chunks)
#pragma unroll
        for (int it = 0; it < 2; it++) {
            int c = tid + it * 256;
            int r = c >> 2, kk = (c & 3) * 8;
            uint4 vh = make_uint4(0, 0, 0, 0), vl = make_uint4(0, 0, 0, 0);
            int ar = row0 + r;
            if (ar < Nn) {
                vh = *reinterpret_cast<const uint4*>(Ahi + (size_t)ar * K + kc0 + kk);
                vl = *reinterpret_cast<const uint4*>(Alo + (size_t)ar * K + kc0 + kk);
            }
            *reinterpret_cast<uint4*>(sAhi + r * SROW + kk) = vh;
            *reinterpret_cast<uint4*>(sAlo + r * SROW + kk) = vl;
            vh = *reinterpret_cast<const uint4*>(g_Bhi + (size_t)(n0 + r) * K + kc0 + kk);
            vl = *reinterpret_cast<const uint4*>(g_Blo + (size_t)(n0 + r) * K + kc0 + kk);
            *reinterpret_cast<uint4*>(sBhi + r * SROW + kk) = vh;
            *reinterpret_cast<uint4*>(sBlo + r * SROW + kk) = vl;
        }
        __syncthreads();

#pragma unroll
        for (int ks = 0; ks < 2; ks++) {
            const int kb = ks * 16;
            uint32_t a_f[4][4], b_h[4][2], b_l[4][2];
            // B frags (hi & lo)
#pragma unroll
            for (int ni = 0; ni < 4; ni++) {
                const __nv_bfloat16* bb = sBhi + (wc * 32 + ni * 8 + tr) * SROW + kb + tc;
                b_h[ni][0] = *reinterpret_cast<const uint32_t*>(bb);
                b_h[ni][1] = *reinterpret_cast<const uint32_t*>(bb + 8);
                const __nv_bfloat16* bl = sBlo + (wc * 32 + ni * 8 + tr) * SROW + kb + tc;
                b_l[ni][0] = *reinterpret_cast<const uint32_t*>(bl);
                b_l[ni][1] = *reinterpret_cast<const uint32_t*>(bl + 8);
            }
            // A hi frags
#pragma unroll
            for (int mi = 0; mi < 4; mi++) {
                const __nv_bfloat16* ab = sAhi + (wr * 64 + mi * 16 + tr) * SROW + kb + tc;
                a_f[mi][0] = *reinterpret_cast<const uint32_t*>(ab);
                a_f[mi][1] = *reinterpret_cast<const uint32_t*>(ab + 8 * SROW);
                a_f[mi][2] = *reinterpret_cast<const uint32_t*>(ab + 8);
                a_f[mi][3] = *reinterpret_cast<const uint32_t*>(ab + 8 * SROW + 8);
            }
            // pass 1: A_hi * B_hi ; pass 2: A_hi * B_lo
#pragma unroll
            for (int mi = 0; mi < 4; mi++)
#pragma unroll
                for (int ni = 0; ni < 4; ni++) {
                    mma16816(acc[mi][ni], a_f[mi], b_h[ni]);
                    mma16816(acc[mi][ni], a_f[mi], b_l[ni]);
                }
            // A lo frags (reuse regs), pass 3: A_lo * B_hi
#pragma unroll
            for (int mi = 0; mi < 4; mi++) {
                const __nv_bfloat16* ab = sAlo + (wr * 64 + mi * 16 + tr) * SROW + kb + tc;
                a_f[mi][0] = *reinterpret_cast<const uint32_t*>(ab);
                a_f[mi][1] = *reinterpret_cast<const uint32_t*>(ab + 8 * SROW);
                a_f[mi][2] = *reinterpret_cast<const uint32_t*>(ab + 8);
                a_f[mi][3] = *reinterpret_cast<const uint32_t*>(ab + 8 * SROW + 8);
            }
#pragma unroll
            for (int mi = 0; mi < 4; mi++)
#pragma unroll
                for (int ni = 0; ni < 4; ni++)
                    mma16816(acc[mi][ni], a_f[mi], b_h[ni]);
        }
        __syncthreads();
    }

    // epilogue: direct store to Hout / Rout (+pb)
    const bool isR = (n0 >= Dhalf);
    float* dst = isR ? Rout : Hout;
    const int cbase = (isR ? (n0 - Dhalf) : n0) + wc * 32;
#pragma unroll
    for (int mi = 0; mi < 4; mi++) {
        int r1 = row0 + wr * 64 + mi * 16 + tr;
        int r2 = r1 + 8;
#pragma unroll
        for (int ni = 0; ni < 4; ni++) {
            int cc = cbase + ni * 8 + tc;
            float bx = 0.f, by = 0.f;
            if (isR) { bx = pb[cc]; by = pb[cc + 1]; }
            if (r1 < Nn) {
                float2 o = make_float2(acc[mi][ni][0] + bx, acc[mi][ni][1] + by);
                *reinterpret_cast<float2*>(dst + (size_t)r1 * Dhalf + cc) = o;
            }
            if (r2 < Nn) {
                float2 o = make_float2(acc[mi][ni][2] + bx, acc[mi][ni][3] + by);
                *reinterpret_cast<float2*>(dst + (size_t)r2 * Dhalf + cc) = o;
            }
        }
    }
}

// =========================== scores ===========================
__global__ void k_scores(const float* __restrict__ H, const float* __restrict__ a_s,
                         const float* __restrict__ a_d, int Hh, int C) {
    int idx = blockIdx.x * blockDim.x + threadIdx.x;
    if (idx >= Nn * Hh) return;
    int n = idx / Hh, h = idx - n * Hh;
    int D = Hh * C;
    const float4* hp = reinterpret_cast<const float4*>(H + (size_t)n * D + h * C);
    const float4* sp = reinterpret_cast<const float4*>(a_s + h * C);
    const float4* dp = reinterpret_cast<const float4*>(a_d + h * C);
    float as = 0.f, ad = 0.f;
    for (int c = 0; c < C / 4; c++) {
        float4 v = hp[c], s4 = sp[c], d4 = dp[c];
        as = fmaf(v.x, s4.x, fmaf(v.y, s4.y, fmaf(v.z, s4.z, fmaf(v.w, s4.w, as))));
        ad = fmaf(v.x, d4.x, fmaf(v.y, d4.y, fmaf(v.z, d4.z, fmaf(v.w, d4.w, ad))));
    }
    g_asrc[idx] = as;
    g_adst[idx] = ad;
}

// ============ fused GAT gather + softmax + bias + LN + residual + ELU ============
template<int Hh, int C>
__global__ __launch_bounds__(256) void k_gat(
        const float* __restrict__ H, const float* __restrict__ R,
        const float* __restrict__ bias, const float* __restrict__ gam,
        const float* __restrict__ bet, float* __restrict__ Xout) {
    constexpr int D = Hh * C;
    constexpr int NF4 = D / 4;
    constexpr int IT = NF4 / 32;
    constexpr int C4 = C / 4;

    int n = blockIdx.x * (blockDim.x >> 5) + (threadIdx.x >> 5);
    if (n >= Nn) return;
    int lane = threadIdx.x & 31;

    float adst_l = (lane < Hh) ? g_adst[n * Hh + lane] : 0.f;
    float denom_l = 0.f;
    float4 acc[IT];
#pragma unroll
    for (int t = 0; t < IT; t++) acc[t] = make_float4(0.f, 0.f, 0.f, 0.f);

    const float4* H4 = reinterpret_cast<const float4*>(H);

    int beg = g_off[n];
    int deg = g_deg[n];
    int s_next = (deg > 0) ? g_srcs[beg] : n;

    for (int e = 0; e <= deg; e++) {
        int s = s_next;
        s_next = (e + 1 < deg) ? g_srcs[beg + e + 1] : n;
        float w_l = 0.f;
        if (lane < Hh) {
            float ev = lrelu(g_asrc[s * Hh + lane] + adst_l);
            w_l = __expf(ev);
            denom_l += w_l;
        }
#pragma unroll
        for (int t = 0; t < IT; t++) {
            int j = lane + t * 32;
            float wj = __shfl_sync(0xFFFFFFFFu, w_l, j / C4);
            float4 hv = H4[(size_t)s * NF4 + j];
            acc[t].x = fmaf(wj, hv.x, acc[t].x);
            acc[t].y = fmaf(wj, hv.y, acc[t].y);
            acc[t].z = fmaf(wj, hv.z, acc[t].z);
            acc[t].w = fmaf(wj, hv.w, acc[t].w);
        }
    }

    float vals[IT * 4];
    float s1 = 0.f, s2 = 0.f;
    const float4* B4 = reinterpret_cast<const float4*>(bias);
#pragma unroll
    for (int t = 0; t < IT; t++) {
        int j = lane + t * 32;
        float dj = __shfl_sync(0xFFFFFFFFu, denom_l, j / C4) + 1e-16f;
        float inv = 1.0f / dj;
        float4 bv = B4[j];
        float4 v = make_float4(fmaf(acc[t].x, inv, bv.x), fmaf(acc[t].y, inv, bv.y),
                               fmaf(acc[t].z, inv, bv.z), fmaf(acc[t].w, inv, bv.w));
        vals[t * 4 + 0] = v.x; vals[t * 4 + 1] = v.y;
        vals[t * 4 + 2] = v.z; vals[t * 4 + 3] = v.w;
        s1 += v.x + v.y + v.z + v.w;
        s2 = fmaf(v.x, v.x, fmaf(v.y, v.y, fmaf(v.z, v.z, fmaf(v.w, v.w, s2))));
    }
#pragma unroll
    for (int o = 16; o > 0; o >>= 1) {
        s1 += __shfl_xor_sync(0xFFFFFFFFu, s1, o);
        s2 += __shfl_xor_sync(0xFFFFFFFFu, s2, o);
    }
    float mean = s1 / (float)D;
    float var = s2 / (float)D - mean * mean;
    float inv = rsqrtf(var + 1e-5f);

    const float4* G4 = reinterpret_cast<const float4*>(gam);
    const float4* E4 = reinterpret_cast<const float4*>(bet);
    const float4* R4 = reinterpret_cast<const float4*>(R);
    float4* O4 = reinterpret_cast<float4*>(Xout);
#pragma unroll
    for (int t = 0; t < IT; t++) {
        int j = lane + t * 32;
        float4 gv = G4[j], ev = E4[j], rv = R4[(size_t)n * NF4 + j];
        float x0 = (vals[t * 4 + 0] - mean) * inv * gv.x + ev.x + rv.x;
        float x1 = (vals[t * 4 + 1] - mean) * inv * gv.y + ev.y + rv.y;
        float x2 = (vals[t * 4 + 2] - mean) * inv * gv.z + ev.z + rv.z;
        float x3 = (vals[t * 4 + 3] - mean) * inv * gv.w + ev.w + rv.w;
        float4 o;
        o.x = x0 > 0.f ? x0 : expm1f(x0);
        o.y = x1 > 0.f ? x1 : expm1f(x1);
        o.z = x2 > 0.f ? x2 : expm1f(x2);
        o.w = x3 > 0.f ? x3 : expm1f(x3);
        O4[(size_t)n * NF4 + j] = o;
    }
}

// =========================== pooling ===========================
__global__ void k_pool_zero(float* __restrict__ out) {
    int idx = blockIdx.x * blockDim.x + threadIdx.x;
    if (idx < Gg * 128) out[idx] = 0.f;
    if (idx < Gg) g_cnt[idx] = 0.f;
}
__global__ void k_pool(const int* __restrict__ batch, float* __restrict__ out) {
    int idx = blockIdx.x * blockDim.x + threadIdx.x;
    if (idx >= Nn * 32) return;
    int n = idx >> 5, j = idx & 31;
    int b = batch[n];
    float4 v = reinterpret_cast<const float4*>(g_X3)[n * 32 + j];
    red4(&out[b * 128 + j * 4], v);
    if (j == 0) atomicAdd(&g_cnt[b], 1.0f);
}
__global__ void k_pool_div(float* __restrict__ out) {
    int idx = blockIdx.x * blockDim.x + threadIdx.x;
    if (idx >= Gg * 128) return;
    out[idx] /= fmaxf(g_cnt[idx >> 7], 1.0f);
}

// =========================== host ===========================
extern "C" void kernel_launch(void* const* d_in, const int* in_sizes, int n_in,
                              void* d_out, int out_size) {
    const float* x   = (const float*)d_in[0];
    const int* ei    = (const int*)d_in[1];
    const int* batch = (const int*)d_in[2];
    const float* W1 = (const float*)d_in[3],  *as1 = (const float*)d_in[4],
               *ad1 = (const float*)d_in[5],  *b1  = (const float*)d_in[6],
               *g1  = (const float*)d_in[7],  *be1 = (const float*)d_in[8],
               *pw1 = (const float*)d_in[9],  *pb1 = (const float*)d_in[10];
    const float* W2 = (const float*)d_in[11], *as2 = (const float*)d_in[12],
               *ad2 = (const float*)d_in[13], *b2  = (const float*)d_in[14],
               *g2  = (const float*)d_in[15], *be2 = (const float*)d_in[16],
               *pw2 = (const float*)d_in[17], *pb2 = (const float*)d_in[18];
    const float* W3 = (const float*)d_in[19], *as3 = (const float*)d_in[20],
               *ad3 = (const float*)d_in[21], *b3  = (const float*)d_in[22],
               *g3  = (const float*)d_in[23], *be3 = (const float*)d_in[24],
               *pw3 = (const float*)d_in[25], *pb3 = (const float*)d_in[26];
    float* out = (float*)d_out;

    void *pH_, *pR_, *pX1_, *pX2_, *pX3_, *pAhi_, *pAlo_;
    cudaGetSymbolAddress(&pH_,  g_H);
    cudaGetSymbolAddress(&pR_,  g_R);
    cudaGetSymbolAddress(&pX1_, g_X1);
    cudaGetSymbolAddress(&pX2_, g_X2);
    cudaGetSymbolAddress(&pX3_, g_X3);
    cudaGetSymbolAddress(&pAhi_, g_Ahi);
    cudaGetSymbolAddress(&pAlo_, g_Alo);
    float* pH  = (float*)pH_;
    float* pR  = (float*)pR_;
    float* pX1 = (float*)pX1_;
    float* pX2 = (float*)pX2_;
    float* pX3 = (float*)pX3_;
    __nv_bfloat16* pAhi = (__nv_bfloat16*)pAhi_;
    __nv_bfloat16* pAlo = (__nv_bfloat16*)pAlo_;

    const int TB = 256;
    const int MT = (Nn + 127) / 128;   // 391 M-tiles

    // ---- CSR build ----
    k_zero_deg<<<(Nn + TB - 1) / TB, TB>>>();
    k_hist<<<(Ee + TB - 1) / TB, TB>>>(ei);
    k_scan1<<<NSCAN_BLK, 256>>>();
    k_scan2<<<1, 256>>>();
    k_scan3<<<(Nn + TB - 1) / TB, TB>>>();
    k_scatter<<<(Ee + TB - 1) / TB, TB>>>(ei);

    // ---- Layer 1: 128 -> 8x32 (D=256) ----
    {
        int K = 128, Dh = 256;
        k_cvt<<<(Nn * K / 4 + TB - 1) / TB, TB>>>(x, pAhi, pAlo, Nn * K / 4);
        k_prepack<<<(2 * Dh * K + TB - 1) / TB, TB>>>(W1, pw1, K, Dh);
        k_hgemm<<<dim3(2 * Dh / 128, MT), 256>>>(pAhi, pAlo, pb1, pH, pR, K, Dh);
        k_scores<<<(Nn * 8 + TB - 1) / TB, TB>>>(pH, as1, ad1, 8, 32);
        k_gat<8, 32><<<(Nn * 32 + TB - 1) / TB, TB>>>(pH, pR, b1, g1, be1, pX1);
    }
    // ---- Layer 2: 256 -> 4x32 (D=128) ----
    {
        int K = 256, Dh = 128;
        k_cvt<<<(Nn * K / 4 + TB - 1) / TB, TB>>>(pX1, pAhi, pAlo, Nn * K / 4);
        k_prepack<<<(2 * Dh * K + TB - 1) / TB, TB>>>(W2, pw2, K, Dh);
        k_hgemm<<<dim3(2 * Dh / 128, MT), 256>>>(pAhi, pAlo, pb2, pH, pR, K, Dh);
        k_scores<<<(Nn * 4 + TB - 1) / TB, TB>>>(pH, as2, ad2, 4, 32);
        k_gat<4, 32><<<(Nn * 32 + TB - 1) / TB, TB>>>(pH, pR, b2, g2, be2, pX2);
    }
    // ---- Layer 3: 128 -> 1x128 (D=128) ----
    {
        int K = 128, Dh = 128;
        k_cvt<<<(Nn * K / 4 + TB - 1) / TB, TB>>>(pX2, pAhi, pAlo, Nn * K / 4);
        k_prepack<<<(2 * Dh * K + TB - 1) / TB, TB>>>(W3, pw3, K, Dh);
        k_hgemm<<<dim3(2 * Dh / 128, MT), 256>>>(pAhi, pAlo, pb3, pH, pR, K, Dh);
        k_scores<<<(Nn * 1 + TB - 1) / TB, TB>>>(pH, as3, ad3, 1, 128);
        k_gat<1, 128><<<(Nn * 32 + TB - 1) / TB, TB>>>(pH, pR, b3, g3, be3, pX3);
    }

    // ---- pooling ----
    k_pool_zero<<<(Gg * 128 + TB - 1) / TB, TB>>>(out);
    k_pool<<<((size_t)Nn * 32 + TB - 1) / TB, TB>>>(batch, out);
    k_pool_div<<<(Gg * 128 + TB - 1) / TB, TB>>>(out);
}

// round 5
// speedup vs baseline: 2.3116x; 1.1027x over previous
#include <cuda_runtime.h>
#include <cuda_bf16.h>
#include <math.h>
#include <stdint.h>

#define Nn 50000
#define Ee 800000
#define Gg 512
#define NSCAN_BLK 196          // ceil(50000/256)

// ---------------- scratch ----------------
__device__ __align__(256) float g_H[Nn * 256];
__device__ __align__(256) float g_R[Nn * 256];
__device__ __align__(256) float g_X3[Nn * 128];
__device__ __align__(256) float g_asrc[Nn * 8];
__device__ __align__(256) float g_adst[Nn * 8];
__device__ __align__(256) float g_cnt[Gg];
// bf16 hi/lo split buffers
__device__ __align__(256) __nv_bfloat16 g_Ahi[Nn * 256];
__device__ __align__(256) __nv_bfloat16 g_Alo[Nn * 256];
__device__ __align__(256) __nv_bfloat16 g_Bhi[512 * 256];
__device__ __align__(256) __nv_bfloat16 g_Blo[512 * 256];
// CSR
__device__ int g_deg[Nn];
__device__ int g_off[Nn];
__device__ int g_cur[Nn];
__device__ int g_srcs[Ee];
__device__ int g_bsum[256];

__device__ __forceinline__ float lrelu(float x) { return x > 0.0f ? x : 0.2f * x; }
__device__ __forceinline__ void red4(float* p, float4 v) {
    atomicAdd(reinterpret_cast<float4*>(p), v);
}

// =========================== CSR build ===========================
__global__ void k_zero_deg() {
    int i = blockIdx.x * blockDim.x + threadIdx.x;
    if (i < Nn) g_deg[i] = 0;
}
__global__ void k_hist(const int* __restrict__ ei) {
    int e = blockIdx.x * blockDim.x + threadIdx.x;
    if (e < Ee) atomicAdd(&g_deg[ei[Ee + e]], 1);
}
__global__ void k_scan1() {
    __shared__ int sh[256];
    int tid = threadIdx.x;
    int i = blockIdx.x * 256 + tid;
    int v = (i < Nn) ? g_deg[i] : 0;
    sh[tid] = v; __syncthreads();
    for (int off = 1; off < 256; off <<= 1) {
        int t = (tid >= off) ? sh[tid - off] : 0;
        __syncthreads();
        sh[tid] += t;
        __syncthreads();
    }
    if (i < Nn) g_off[i] = sh[tid] - v;
    if (tid == 255) g_bsum[blockIdx.x] = sh[255];
}
__global__ void k_scan2() {
    __shared__ int sh[256];
    int tid = threadIdx.x;
    int v = (tid < NSCAN_BLK) ? g_bsum[tid] : 0;
    sh[tid] = v; __syncthreads();
    for (int off = 1; off < 256; off <<= 1) {
        int t = (tid >= off) ? sh[tid - off] : 0;
        __syncthreads();
        sh[tid] += t;
        __syncthreads();
    }
    if (tid < NSCAN_BLK) g_bsum[tid] = sh[tid] - v;
}
__global__ void k_scan3() {
    int i = blockIdx.x * blockDim.x + threadIdx.x;
    if (i < Nn) {
        g_off[i] += g_bsum[i >> 8];
        g_cur[i] = 0;
    }
}
__global__ void k_scatter(const int* __restrict__ ei) {
    int e = blockIdx.x * blockDim.x + threadIdx.x;
    if (e >= Ee) return;
    int d = ei[Ee + e];
    int pos = g_off[d] + atomicAdd(&g_cur[d], 1);
    g_srcs[pos] = ei[e];
}

// =========================== fp32 -> bf16 hi/lo split (layer-1 input only) ===========================
__global__ void k_cvt(const float* __restrict__ X, __nv_bfloat16* __restrict__ hi,
                      __nv_bfloat16* __restrict__ lo, int total4) {
    int i = blockIdx.x * blockDim.x + threadIdx.x;
    if (i >= total4) return;
    float4 v = reinterpret_cast<const float4*>(X)[i];
    __nv_bfloat16 h0 = __float2bfloat16(v.x), h1 = __float2bfloat16(v.y);
    __nv_bfloat16 h2 = __float2bfloat16(v.z), h3 = __float2bfloat16(v.w);
    __nv_bfloat16 l0 = __float2bfloat16(v.x - __bfloat162float(h0));
    __nv_bfloat16 l1 = __float2bfloat16(v.y - __bfloat162float(h1));
    __nv_bfloat16 l2 = __float2bfloat16(v.z - __bfloat162float(h2));
    __nv_bfloat16 l3 = __float2bfloat16(v.w - __bfloat162float(h3));
    __nv_bfloat162* H2 = reinterpret_cast<__nv_bfloat162*>(hi);
    __nv_bfloat162* L2 = reinterpret_cast<__nv_bfloat162*>(lo);
    H2[i * 2]     = __nv_bfloat162(h0, h1);
    H2[i * 2 + 1] = __nv_bfloat162(h2, h3);
    L2[i * 2]     = __nv_bfloat162(l0, l1);
    L2[i * 2 + 1] = __nv_bfloat162(l2, l3);
}

// weights: Bt[n][k] = (n<Dhalf ? W[k][n] : pw[k][n-Dhalf]), split hi/lo
__global__ void k_prepack(const float* __restrict__ W, const float* __restrict__ pw,
                          int K, int Dhalf) {
    int idx = blockIdx.x * blockDim.x + threadIdx.x;
    int Ncat = 2 * Dhalf;
    if (idx >= Ncat * K) return;
    int n = idx / K, k = idx - n * K;
    float w = (n < Dhalf) ? W[(size_t)k * Dhalf + n] : pw[(size_t)k * Dhalf + (n - Dhalf)];
    __nv_bfloat16 h = __float2bfloat16(w);
    g_Bhi[idx] = h;
    g_Blo[idx] = __float2bfloat16(w - __bfloat162float(h));
}

// =========================== HMMA GEMM (cp.async double-buffered) ===========================
#define SROW 40         // padded smem row stride in bf16 elems (80B)
#define STAGE_BYTES 40960
#define OFF_AHI 0
#define OFF_ALO 10240
#define OFF_BHI 20480
#define OFF_BLO 30720

__device__ __forceinline__ void mma16816(float* d, const uint32_t* a, const uint32_t* b) {
    asm volatile(
        "mma.sync.aligned.m16n8k16.row.col.f32.bf16.bf16.f32 "
        "{%0,%1,%2,%3}, {%4,%5,%6,%7}, {%8,%9}, {%0,%1,%2,%3};"
        : "+f"(d[0]), "+f"(d[1]), "+f"(d[2]), "+f"(d[3])
        : "r"(a[0]), "r"(a[1]), "r"(a[2]), "r"(a[3]), "r"(b[0]), "r"(b[1]));
}

__device__ __forceinline__ uint32_t smem_u32(const void* p) {
    uint32_t a;
    asm("{ .reg .u64 t; cvta.to.shared.u64 t, %1; cvt.u32.u64 %0, t; }" : "=r"(a) : "l"(p));
    return a;
}

__device__ __forceinline__ void cp16(uint32_t dst, const void* src, bool ok) {
    asm volatile(
        "{\n\t.reg .pred p;\n\tsetp.ne.u32 p, %2, 0;\n\t"
        "@p cp.async.cg.shared.global [%0], [%1], 16;\n\t"
        "@!p cp.async.cg.shared.global [%0], [%1], 16, 0;\n\t}"
        :: "r"(dst), "l"(src), "r"((unsigned)ok) : "memory");
}

__global__ __launch_bounds__(256) void k_hgemm(
        const __nv_bfloat16* __restrict__ Ahi, const __nv_bfloat16* __restrict__ Alo,
        const float* __restrict__ pb, float* __restrict__ Hout, float* __restrict__ Rout,
        int K, int Dhalf) {
    extern __shared__ __align__(16) char smem[];
    const uint32_t sbase = smem_u32(smem);

    const int tid = threadIdx.x;
    const int wid = tid >> 5, lane = tid & 31;
    const int row0 = blockIdx.y * 128;
    const int n0 = blockIdx.x * 128;
    const int KC = K >> 5;        // 32-wide k chunks
    const int wr = wid >> 2;      // 0..1
    const int wc = wid & 3;       // 0..3
    const int tr = lane >> 2;     // 0..7
    const int tc = (lane & 3) * 2;

    const int lr = tid >> 2;            // load row 0..63 (x2 iters)
    const int lk = (tid & 3) * 8;       // k element offset 0,8,16,24

    float acc[4][4][4];
#pragma unroll
    for (int mi = 0; mi < 4; mi++)
#pragma unroll
        for (int ni = 0; ni < 4; ni++)
#pragma unroll
            for (int q = 0; q < 4; q++) acc[mi][ni][q] = 0.f;

    // ---- async load of one 128x32 k-chunk into stage ----
    auto load_stage = [&](int stage, int kc) {
        const uint32_t sb = sbase + stage * STAGE_BYTES;
        const int kofs = kc * 32 + lk;
#pragma unroll
        for (int it = 0; it < 2; it++) {
            int r = lr + it * 64;
            uint32_t so = (uint32_t)(r * SROW + lk) * 2;
            int ar = row0 + r;
            bool ok = ar < Nn;
            int arc = ok ? ar : 0;
            cp16(sb + OFF_AHI + so, Ahi + (size_t)arc * K + kofs, ok);
            cp16(sb + OFF_ALO + so, Alo + (size_t)arc * K + kofs, ok);
            cp16(sb + OFF_BHI + so, g_Bhi + (size_t)(n0 + r) * K + kofs, true);
            cp16(sb + OFF_BLO + so, g_Blo + (size_t)(n0 + r) * K + kofs, true);
        }
        asm volatile("cp.async.commit_group;" ::: "memory");
    };

    load_stage(0, 0);

    for (int kc = 0; kc < KC; kc++) {
        const int stage = kc & 1;
        if (kc + 1 < KC) {
            load_stage((kc + 1) & 1, kc + 1);
            asm volatile("cp.async.wait_group 1;" ::: "memory");
        } else {
            asm volatile("cp.async.wait_group 0;" ::: "memory");
        }
        __syncthreads();

        const __nv_bfloat16* sAhi = reinterpret_cast<const __nv_bfloat16*>(smem + stage * STAGE_BYTES + OFF_AHI);
        const __nv_bfloat16* sAlo = reinterpret_cast<const __nv_bfloat16*>(smem + stage * STAGE_BYTES + OFF_ALO);
        const __nv_bfloat16* sBhi = reinterpret_cast<const __nv_bfloat16*>(smem + stage * STAGE_BYTES + OFF_BHI);
        const __nv_bfloat16* sBlo = reinterpret_cast<const __nv_bfloat16*>(smem + stage * STAGE_BYTES + OFF_BLO);

#pragma unroll
        for (int ks = 0; ks < 2; ks++) {
            const int kb = ks * 16;
            uint32_t a_f[4][4], b_h[4][2], b_l[4][2];
#pragma unroll
            for (int ni = 0; ni < 4; ni++) {
                const __nv_bfloat16* bb = sBhi + (wc * 32 + ni * 8 + tr) * SROW + kb + tc;
                b_h[ni][0] = *reinterpret_cast<const uint32_t*>(bb);
                b_h[ni][1] = *reinterpret_cast<const uint32_t*>(bb + 8);
                const __nv_bfloat16* bl = sBlo + (wc * 32 + ni * 8 + tr) * SROW + kb + tc;
                b_l[ni][0] = *reinterpret_cast<const uint32_t*>(bl);
                b_l[ni][1] = *reinterpret_cast<const uint32_t*>(bl + 8);
            }
#pragma unroll
            for (int mi = 0; mi < 4; mi++) {
                const __nv_bfloat16* ab = sAhi + (wr * 64 + mi * 16 + tr) * SROW + kb + tc;
                a_f[mi][0] = *reinterpret_cast<const uint32_t*>(ab);
                a_f[mi][1] = *reinterpret_cast<const uint32_t*>(ab + 8 * SROW);
                a_f[mi][2] = *reinterpret_cast<const uint32_t*>(ab + 8);
                a_f[mi][3] = *reinterpret_cast<const uint32_t*>(ab + 8 * SROW + 8);
            }
#pragma unroll
            for (int mi = 0; mi < 4; mi++)
#pragma unroll
                for (int ni = 0; ni < 4; ni++) {
                    mma16816(acc[mi][ni], a_f[mi], b_h[ni]);
                    mma16816(acc[mi][ni], a_f[mi], b_l[ni]);
                }
#pragma unroll
            for (int mi = 0; mi < 4; mi++) {
                const __nv_bfloat16* ab = sAlo + (wr * 64 + mi * 16 + tr) * SROW + kb + tc;
                a_f[mi][0] = *reinterpret_cast<const uint32_t*>(ab);
                a_f[mi][1] = *reinterpret_cast<const uint32_t*>(ab + 8 * SROW);
                a_f[mi][2] = *reinterpret_cast<const uint32_t*>(ab + 8);
                a_f[mi][3] = *reinterpret_cast<const uint32_t*>(ab + 8 * SROW + 8);
            }
#pragma unroll
            for (int mi = 0; mi < 4; mi++)
#pragma unroll
                for (int ni = 0; ni < 4; ni++)
                    mma16816(acc[mi][ni], a_f[mi], b_h[ni]);
        }
        __syncthreads();
    }

    const bool isR = (n0 >= Dhalf);
    float* dst = isR ? Rout : Hout;
    const int cbase = (isR ? (n0 - Dhalf) : n0) + wc * 32;
#pragma unroll
    for (int mi = 0; mi < 4; mi++) {
        int r1 = row0 + wr * 64 + mi * 16 + tr;
        int r2 = r1 + 8;
#pragma unroll
        for (int ni = 0; ni < 4; ni++) {
            int cc = cbase + ni * 8 + tc;
            float bx = 0.f, by = 0.f;
            if (isR) { bx = pb[cc]; by = pb[cc + 1]; }
            if (r1 < Nn) {
                float2 o = make_float2(acc[mi][ni][0] + bx, acc[mi][ni][1] + by);
                *reinterpret_cast<float2*>(dst + (size_t)r1 * Dhalf + cc) = o;
            }
            if (r2 < Nn) {
                float2 o = make_float2(acc[mi][ni][2] + bx, acc[mi][ni][3] + by);
                *reinterpret_cast<float2*>(dst + (size_t)r2 * Dhalf + cc) = o;
            }
        }
    }
}

// =========================== scores ===========================
__global__ void k_scores(const float* __restrict__ H, const float* __restrict__ a_s,
                         const float* __restrict__ a_d, int Hh, int C) {
    int idx = blockIdx.x * blockDim.x + threadIdx.x;
    if (idx >= Nn * Hh) return;
    int n = idx / Hh, h = idx - n * Hh;
    int D = Hh * C;
    const float4* hp = reinterpret_cast<const float4*>(H + (size_t)n * D + h * C);
    const float4* sp = reinterpret_cast<const float4*>(a_s + h * C);
    const float4* dp = reinterpret_cast<const float4*>(a_d + h * C);
    float as = 0.f, ad = 0.f;
    for (int c = 0; c < C / 4; c++) {
        float4 v = hp[c], s4 = sp[c], d4 = dp[c];
        as = fmaf(v.x, s4.x, fmaf(v.y, s4.y, fmaf(v.z, s4.z, fmaf(v.w, s4.w, as))));
        ad = fmaf(v.x, d4.x, fmaf(v.y, d4.y, fmaf(v.z, d4.z, fmaf(v.w, d4.w, ad))));
    }
    g_asrc[idx] = as;
    g_adst[idx] = ad;
}

// ============ fused GAT gather + softmax + bias + LN + residual + ELU ============
// WB16: write bf16 hi/lo split (next layer's GEMM A) instead of fp32.
template<int Hh, int C, bool WB16>
__global__ __launch_bounds__(256) void k_gat(
        const float* __restrict__ H, const float* __restrict__ R,
        const float* __restrict__ bias, const float* __restrict__ gam,
        const float* __restrict__ bet, float* __restrict__ Xout,
        __nv_bfloat16* __restrict__ Ohi, __nv_bfloat16* __restrict__ Olo) {
    constexpr int D = Hh * C;
    constexpr int NF4 = D / 4;
    constexpr int IT = NF4 / 32;
    constexpr int C4 = C / 4;

    int n = blockIdx.x * (blockDim.x >> 5) + (threadIdx.x >> 5);
    if (n >= Nn) return;
    int lane = threadIdx.x & 31;

    float adst_l = (lane < Hh) ? g_adst[n * Hh + lane] : 0.f;
    float denom_l = 0.f;
    float4 acc[IT];
#pragma unroll
    for (int t = 0; t < IT; t++) acc[t] = make_float4(0.f, 0.f, 0.f, 0.f);

    const float4* H4 = reinterpret_cast<const float4*>(H);

    int beg = g_off[n];
    int deg = g_deg[n];
    int s_next = (deg > 0) ? g_srcs[beg] : n;

    for (int e = 0; e <= deg; e++) {
        int s = s_next;
        s_next = (e + 1 < deg) ? g_srcs[beg + e + 1] : n;
        float w_l = 0.f;
        if (lane < Hh) {
            float ev = lrelu(g_asrc[s * Hh + lane] + adst_l);
            w_l = __expf(ev);
            denom_l += w_l;
        }
#pragma unroll
        for (int t = 0; t < IT; t++) {
            int j = lane + t * 32;
            float wj = __shfl_sync(0xFFFFFFFFu, w_l, j / C4);
            float4 hv = H4[(size_t)s * NF4 + j];
            acc[t].x = fmaf(wj, hv.x, acc[t].x);
            acc[t].y = fmaf(wj, hv.y, acc[t].y);
            acc[t].z = fmaf(wj, hv.z, acc[t].z);
            acc[t].w = fmaf(wj, hv.w, acc[t].w);
        }
    }

    float vals[IT * 4];
    float s1 = 0.f, s2 = 0.f;
    const float4* B4 = reinterpret_cast<const float4*>(bias);
#pragma unroll
    for (int t = 0; t < IT; t++) {
        int j = lane + t * 32;
        float dj = __shfl_sync(0xFFFFFFFFu, denom_l, j / C4) + 1e-16f;
        float inv = 1.0f / dj;
        float4 bv = B4[j];
        float4 v = make_float4(fmaf(acc[t].x, inv, bv.x), fmaf(acc[t].y, inv, bv.y),
                               fmaf(acc[t].z, inv, bv.z), fmaf(acc[t].w, inv, bv.w));
        vals[t * 4 + 0] = v.x; vals[t * 4 + 1] = v.y;
        vals[t * 4 + 2] = v.z; vals[t * 4 + 3] = v.w;
        s1 += v.x + v.y + v.z + v.w;
        s2 = fmaf(v.x, v.x, fmaf(v.y, v.y, fmaf(v.z, v.z, fmaf(v.w, v.w, s2))));
    }
#pragma unroll
    for (int o = 16; o > 0; o >>= 1) {
        s1 += __shfl_xor_sync(0xFFFFFFFFu, s1, o);
        s2 += __shfl_xor_sync(0xFFFFFFFFu, s2, o);
    }
    float mean = s1 / (float)D;
    float var = s2 / (float)D - mean * mean;
    float inv = rsqrtf(var + 1e-5f);

    const float4* G4 = reinterpret_cast<const float4*>(gam);
    const float4* E4 = reinterpret_cast<const float4*>(bet);
    const float4* R4 = reinterpret_cast<const float4*>(R);
#pragma unroll
    for (int t = 0; t < IT; t++) {
        int j = lane + t * 32;
        float4 gv = G4[j], ev = E4[j], rv = R4[(size_t)n * NF4 + j];
        float x0 = (vals[t * 4 + 0] - mean) * inv * gv.x + ev.x + rv.x;
        float x1 = (vals[t * 4 + 1] - mean) * inv * gv.y + ev.y + rv.y;
        float x2 = (vals[t * 4 + 2] - mean) * inv * gv.z + ev.z + rv.z;
        float x3 = (vals[t * 4 + 3] - mean) * inv * gv.w + ev.w + rv.w;
        float4 o;
        o.x = x0 > 0.f ? x0 : expm1f(x0);
        o.y = x1 > 0.f ? x1 : expm1f(x1);
        o.z = x2 > 0.f ? x2 : expm1f(x2);
        o.w = x3 > 0.f ? x3 : expm1f(x3);
        if (WB16) {
            __nv_bfloat16 h0 = __float2bfloat16(o.x), h1 = __float2bfloat16(o.y);
            __nv_bfloat16 h2 = __float2bfloat16(o.z), h3 = __float2bfloat16(o.w);
            __nv_bfloat16 l0 = __float2bfloat16(o.x - __bfloat162float(h0));
            __nv_bfloat16 l1 = __float2bfloat16(o.y - __bfloat162float(h1));
            __nv_bfloat16 l2 = __float2bfloat16(o.z - __bfloat162float(h2));
            __nv_bfloat16 l3 = __float2bfloat16(o.w - __bfloat162float(h3));
            __nv_bfloat162* OH = reinterpret_cast<__nv_bfloat162*>(Ohi + (size_t)n * D + j * 4);
            __nv_bfloat162* OL = reinterpret_cast<__nv_bfloat162*>(Olo + (size_t)n * D + j * 4);
            OH[0] = __nv_bfloat162(h0, h1);
            OH[1] = __nv_bfloat162(h2, h3);
            OL[0] = __nv_bfloat162(l0, l1);
            OL[1] = __nv_bfloat162(l2, l3);
        } else {
            reinterpret_cast<float4*>(Xout)[(size_t)n * NF4 + j] = o;
        }
    }
}

// =========================== pooling ===========================
__global__ void k_pool_zero(float* __restrict__ out) {
    int idx = blockIdx.x * blockDim.x + threadIdx.x;
    if (idx < Gg * 128) out[idx] = 0.f;
    if (idx < Gg) g_cnt[idx] = 0.f;
}
__global__ void k_pool(const int* __restrict__ batch, float* __restrict__ out) {
    int idx = blockIdx.x * blockDim.x + threadIdx.x;
    if (idx >= Nn * 32) return;
    int n = idx >> 5, j = idx & 31;
    int b = batch[n];
    float4 v = reinterpret_cast<const float4*>(g_X3)[n * 32 + j];
    red4(&out[b * 128 + j * 4], v);
    if (j == 0) atomicAdd(&g_cnt[b], 1.0f);
}
__global__ void k_pool_div(float* __restrict__ out) {
    int idx = blockIdx.x * blockDim.x + threadIdx.x;
    if (idx >= Gg * 128) return;
    out[idx] /= fmaxf(g_cnt[idx >> 7], 1.0f);
}

// =========================== host ===========================
extern "C" void kernel_launch(void* const* d_in, const int* in_sizes, int n_in,
                              void* d_out, int out_size) {
    const float* x   = (const float*)d_in[0];
    const int* ei    = (const int*)d_in[1];
    const int* batch = (const int*)d_in[2];
    const float* W1 = (const float*)d_in[3],  *as1 = (const float*)d_in[4],
               *ad1 = (const float*)d_in[5],  *b1  = (const float*)d_in[6],
               *g1  = (const float*)d_in[7],  *be1 = (const float*)d_in[8],
               *pw1 = (const float*)d_in[9],  *pb1 = (const float*)d_in[10];
    const float* W2 = (const float*)d_in[11], *as2 = (const float*)d_in[12],
               *ad2 = (const float*)d_in[13], *b2  = (const float*)d_in[14],
               *g2  = (const float*)d_in[15], *be2 = (const float*)d_in[16],
               *pw2 = (const float*)d_in[17], *pb2 = (const float*)d_in[18];
    const float* W3 = (const float*)d_in[19], *as3 = (const float*)d_in[20],
               *ad3 = (const float*)d_in[21], *b3  = (const float*)d_in[22],
               *g3  = (const float*)d_in[23], *be3 = (const float*)d_in[24],
               *pw3 = (const float*)d_in[25], *pb3 = (const float*)d_in[26];
    float* out = (float*)d_out;

    void *pH_, *pR_, *pX3_, *pAhi_, *pAlo_;
    cudaGetSymbolAddress(&pH_,  g_H);
    cudaGetSymbolAddress(&pR_,  g_R);
    cudaGetSymbolAddress(&pX3_, g_X3);
    cudaGetSymbolAddress(&pAhi_, g_Ahi);
    cudaGetSymbolAddress(&pAlo_, g_Alo);
    float* pH  = (float*)pH_;
    float* pR  = (float*)pR_;
    float* pX3 = (float*)pX3_;
    __nv_bfloat16* pAhi = (__nv_bfloat16*)pAhi_;
    __nv_bfloat16* pAlo = (__nv_bfloat16*)pAlo_;

    cudaFuncSetAttribute(k_hgemm, cudaFuncAttributeMaxDynamicSharedMemorySize, 2 * STAGE_BYTES);

    const int TB = 256;
    const int MT = (Nn + 127) / 128;   // 391 M-tiles

    // ---- CSR build ----
    k_zero_deg<<<(Nn + TB - 1) / TB, TB>>>();
    k_hist<<<(Ee + TB - 1) / TB, TB>>>(ei);
    k_scan1<<<NSCAN_BLK, 256>>>();
    k_scan2<<<1, 256>>>();
    k_scan3<<<(Nn + TB - 1) / TB, TB>>>();
    k_scatter<<<(Ee + TB - 1) / TB, TB>>>(ei);

    // ---- Layer 1: 128 -> 8x32 (D=256) ----
    {
        int K = 128, Dh = 256;
        k_cvt<<<(Nn * K / 4 + TB - 1) / TB, TB>>>(x, pAhi, pAlo, Nn * K / 4);
        k_prepack<<<(2 * Dh * K + TB - 1) / TB, TB>>>(W1, pw1, K, Dh);
        k_hgemm<<<dim3(2 * Dh / 128, MT), 256, 2 * STAGE_BYTES>>>(pAhi, pAlo, pb1, pH, pR, K, Dh);
        k_scores<<<(Nn * 8 + TB - 1) / TB, TB>>>(pH, as1, ad1, 8, 32);
        k_gat<8, 32, true><<<(Nn * 32 + TB - 1) / TB, TB>>>(pH, pR, b1, g1, be1, nullptr, pAhi, pAlo);
    }
    // ---- Layer 2: 256 -> 4x32 (D=128) ----
    {
        int K = 256, Dh = 128;
        k_prepack<<<(2 * Dh * K + TB - 1) / TB, TB>>>(W2, pw2, K, Dh);
        k_hgemm<<<dim3(2 * Dh / 128, MT), 256, 2 * STAGE_BYTES>>>(pAhi, pAlo, pb2, pH, pR, K, Dh);
        k_scores<<<(Nn * 4 + TB - 1) / TB, TB>>>(pH, as2, ad2, 4, 32);
        k_gat<4, 32, true><<<(Nn * 32 + TB - 1) / TB, TB>>>(pH, pR, b2, g2, be2, nullptr, pAhi, pAlo);
    }
    // ---- Layer 3: 128 -> 1x128 (D=128) ----
    {
        int K = 128, Dh = 128;
        k_prepack<<<(2 * Dh * K + TB - 1) / TB, TB>>>(W3, pw3, K, Dh);
        k_hgemm<<<dim3(2 * Dh / 128, MT), 256, 2 * STAGE_BYTES>>>(pAhi, pAlo, pb3, pH, pR, K, Dh);
        k_scores<<<(Nn * 1 + TB - 1) / TB, TB>>>(pH, as3, ad3, 1, 128);
        k_gat<1, 128, false><<<(Nn * 32 + TB - 1) / TB, TB>>>(pH, pR, b3, g3, be3, pX3, nullptr, nullptr);
    }

    // ---- pooling ----
    k_pool_zero<<<(Gg * 128 + TB - 1) / TB, TB>>>(out);
    k_pool<<<((size_t)Nn * 32 + TB - 1) / TB, TB>>>(batch, out);
    k_pool_div<<<(Gg * 128 + TB - 1) / TB, TB>>>(out);
}

// round 6
// speedup vs baseline: 2.3685x; 1.0246x over previous
#include <cuda_runtime.h>
#include <cuda_bf16.h>
#include <math.h>
#include <stdint.h>

#define Nn 50000
#define Ee 800000
#define Gg 512
#define NSCAN_BLK 196          // ceil(50000/256)

// weight pack region offsets (elements)
#define BOFF1 0          // L1: 512 x 128
#define BOFF2 65536      // L2: 256 x 256
#define BOFF3 131072     // L3: 256 x 128
#define BTOT  163840

// ---------------- scratch ----------------
__device__ __align__(256) float g_H[Nn * 256];
__device__ __align__(256) float g_R[Nn * 256];
__device__ __align__(256) float g_X3[Nn * 128];
__device__ __align__(256) float g_asrc[Nn * 8];
__device__ __align__(256) float g_adst[Nn * 8];
__device__ __align__(256) float g_cnt[Gg];
// bf16 hi/lo split buffers
__device__ __align__(256) __nv_bfloat16 g_Ahi[Nn * 256];
__device__ __align__(256) __nv_bfloat16 g_Alo[Nn * 256];
__device__ __align__(256) __nv_bfloat16 g_Bhi[BTOT];
__device__ __align__(256) __nv_bfloat16 g_Blo[BTOT];
// CSR
__device__ int g_deg[Nn];
__device__ int g_off[Nn];
__device__ int g_cur[Nn];
__device__ int g_srcs[Ee];
__device__ int g_bsum[256];

__device__ __forceinline__ float lrelu(float x) { return x > 0.0f ? x : 0.2f * x; }
__device__ __forceinline__ void red4(float* p, float4 v) {
    atomicAdd(reinterpret_cast<float4*>(p), v);
}

// =========================== CSR build ===========================
__global__ void k_zero_deg() {
    int i = blockIdx.x * blockDim.x + threadIdx.x;
    if (i < Nn) g_deg[i] = 0;
}
__global__ void k_hist(const int* __restrict__ ei) {
    int e = blockIdx.x * blockDim.x + threadIdx.x;
    if (e < Ee) atomicAdd(&g_deg[ei[Ee + e]], 1);
}
__global__ void k_scan1() {
    __shared__ int sh[256];
    int tid = threadIdx.x;
    int i = blockIdx.x * 256 + tid;
    int v = (i < Nn) ? g_deg[i] : 0;
    sh[tid] = v; __syncthreads();
    for (int off = 1; off < 256; off <<= 1) {
        int t = (tid >= off) ? sh[tid - off] : 0;
        __syncthreads();
        sh[tid] += t;
        __syncthreads();
    }
    if (i < Nn) g_off[i] = sh[tid] - v;
    if (tid == 255) g_bsum[blockIdx.x] = sh[255];
}
__global__ void k_scan2() {
    __shared__ int sh[256];
    int tid = threadIdx.x;
    int v = (tid < NSCAN_BLK) ? g_bsum[tid] : 0;
    sh[tid] = v; __syncthreads();
    for (int off = 1; off < 256; off <<= 1) {
        int t = (tid >= off) ? sh[tid - off] : 0;
        __syncthreads();
        sh[tid] += t;
        __syncthreads();
    }
    if (tid < NSCAN_BLK) g_bsum[tid] = sh[tid] - v;
}
__global__ void k_scan3() {
    int i = blockIdx.x * blockDim.x + threadIdx.x;
    if (i < Nn) {
        g_off[i] += g_bsum[i >> 8];
        g_cur[i] = 0;
    }
}
__global__ void k_scatter(const int* __restrict__ ei) {
    int e = blockIdx.x * blockDim.x + threadIdx.x;
    if (e >= Ee) return;
    int d = ei[Ee + e];
    int pos = g_off[d] + atomicAdd(&g_cur[d], 1);
    g_srcs[pos] = ei[e];
}

// =========================== fp32 -> bf16 hi/lo split (layer-1 input only) ===========================
__global__ void k_cvt(const float* __restrict__ X, __nv_bfloat16* __restrict__ hi,
                      __nv_bfloat16* __restrict__ lo, int total4) {
    int i = blockIdx.x * blockDim.x + threadIdx.x;
    if (i >= total4) return;
    float4 v = reinterpret_cast<const float4*>(X)[i];
    __nv_bfloat16 h0 = __float2bfloat16(v.x), h1 = __float2bfloat16(v.y);
    __nv_bfloat16 h2 = __float2bfloat16(v.z), h3 = __float2bfloat16(v.w);
    __nv_bfloat16 l0 = __float2bfloat16(v.x - __bfloat162float(h0));
    __nv_bfloat16 l1 = __float2bfloat16(v.y - __bfloat162float(h1));
    __nv_bfloat16 l2 = __float2bfloat16(v.z - __bfloat162float(h2));
    __nv_bfloat16 l3 = __float2bfloat16(v.w - __bfloat162float(h3));
    __nv_bfloat162* H2 = reinterpret_cast<__nv_bfloat162*>(hi);
    __nv_bfloat162* L2 = reinterpret_cast<__nv_bfloat162*>(lo);
    H2[i * 2]     = __nv_bfloat162(h0, h1);
    H2[i * 2 + 1] = __nv_bfloat162(h2, h3);
    L2[i * 2]     = __nv_bfloat162(l0, l1);
    L2[i * 2 + 1] = __nv_bfloat162(l2, l3);
}

// weights: Bt[n][k] = (n<Dhalf ? W[k][n] : pw[k][n-Dhalf]), split hi/lo, into region at `boff`
__global__ void k_prepack(const float* __restrict__ W, const float* __restrict__ pw,
                          int K, int Dhalf, int boff) {
    int idx = blockIdx.x * blockDim.x + threadIdx.x;
    int Ncat = 2 * Dhalf;
    if (idx >= Ncat * K) return;
    int n = idx / K, k = idx - n * K;
    float w = (n < Dhalf) ? W[(size_t)k * Dhalf + n] : pw[(size_t)k * Dhalf + (n - Dhalf)];
    __nv_bfloat16 h = __float2bfloat16(w);
    g_Bhi[boff + idx] = h;
    g_Blo[boff + idx] = __float2bfloat16(w - __bfloat162float(h));
}

// =========================== HMMA GEMM (cp.async double-buffered) ===========================
#define SROW 40         // padded smem row stride in bf16 elems (80B)
#define STAGE_BYTES 40960
#define OFF_AHI 0
#define OFF_ALO 10240
#define OFF_BHI 20480
#define OFF_BLO 30720

__device__ __forceinline__ void mma16816(float* d, const uint32_t* a, const uint32_t* b) {
    asm volatile(
        "mma.sync.aligned.m16n8k16.row.col.f32.bf16.bf16.f32 "
        "{%0,%1,%2,%3}, {%4,%5,%6,%7}, {%8,%9}, {%0,%1,%2,%3};"
        : "+f"(d[0]), "+f"(d[1]), "+f"(d[2]), "+f"(d[3])
        : "r"(a[0]), "r"(a[1]), "r"(a[2]), "r"(a[3]), "r"(b[0]), "r"(b[1]));
}

__device__ __forceinline__ uint32_t smem_u32(const void* p) {
    uint32_t a;
    asm("{ .reg .u64 t; cvta.to.shared.u64 t, %1; cvt.u32.u64 %0, t; }" : "=r"(a) : "l"(p));
    return a;
}

__device__ __forceinline__ void cp16(uint32_t dst, const void* src, bool ok) {
    asm volatile(
        "{\n\t.reg .pred p;\n\tsetp.ne.u32 p, %2, 0;\n\t"
        "@p cp.async.cg.shared.global [%0], [%1], 16;\n\t"
        "@!p cp.async.cg.shared.global [%0], [%1], 16, 0;\n\t}"
        :: "r"(dst), "l"(src), "r"((unsigned)ok) : "memory");
}

__global__ __launch_bounds__(256) void k_hgemm(
        const __nv_bfloat16* __restrict__ Ahi, const __nv_bfloat16* __restrict__ Alo,
        const __nv_bfloat16* __restrict__ Bhi, const __nv_bfloat16* __restrict__ Blo,
        const float* __restrict__ pb, float* __restrict__ Hout, float* __restrict__ Rout,
        int K, int Dhalf) {
    extern __shared__ __align__(16) char smem[];
    const uint32_t sbase = smem_u32(smem);

    const int tid = threadIdx.x;
    const int wid = tid >> 5, lane = tid & 31;
    const int row0 = blockIdx.y * 128;
    const int n0 = blockIdx.x * 128;
    const int KC = K >> 5;        // 32-wide k chunks
    const int wr = wid >> 2;      // 0..1
    const int wc = wid & 3;       // 0..3
    const int tr = lane >> 2;     // 0..7
    const int tc = (lane & 3) * 2;

    const int lr = tid >> 2;            // load row 0..63 (x2 iters)
    const int lk = (tid & 3) * 8;       // k element offset 0,8,16,24

    float acc[4][4][4];
#pragma unroll
    for (int mi = 0; mi < 4; mi++)
#pragma unroll
        for (int ni = 0; ni < 4; ni++)
#pragma unroll
            for (int q = 0; q < 4; q++) acc[mi][ni][q] = 0.f;

    auto load_stage = [&](int stage, int kc) {
        const uint32_t sb = sbase + stage * STAGE_BYTES;
        const int kofs = kc * 32 + lk;
#pragma unroll
        for (int it = 0; it < 2; it++) {
            int r = lr + it * 64;
            uint32_t so = (uint32_t)(r * SROW + lk) * 2;
            int ar = row0 + r;
            bool ok = ar < Nn;
            int arc = ok ? ar : 0;
            cp16(sb + OFF_AHI + so, Ahi + (size_t)arc * K + kofs, ok);
            cp16(sb + OFF_ALO + so, Alo + (size_t)arc * K + kofs, ok);
            cp16(sb + OFF_BHI + so, Bhi + (size_t)(n0 + r) * K + kofs, true);
            cp16(sb + OFF_BLO + so, Blo + (size_t)(n0 + r) * K + kofs, true);
        }
        asm volatile("cp.async.commit_group;" ::: "memory");
    };

    load_stage(0, 0);

    for (int kc = 0; kc < KC; kc++) {
        const int stage = kc & 1;
        if (kc + 1 < KC) {
            load_stage((kc + 1) & 1, kc + 1);
            asm volatile("cp.async.wait_group 1;" ::: "memory");
        } else {
            asm volatile("cp.async.wait_group 0;" ::: "memory");
        }
        __syncthreads();

        const __nv_bfloat16* sAhi = reinterpret_cast<const __nv_bfloat16*>(smem + stage * STAGE_BYTES + OFF_AHI);
        const __nv_bfloat16* sAlo = reinterpret_cast<const __nv_bfloat16*>(smem + stage * STAGE_BYTES + OFF_ALO);
        const __nv_bfloat16* sBhi = reinterpret_cast<const __nv_bfloat16*>(smem + stage * STAGE_BYTES + OFF_BHI);
        const __nv_bfloat16* sBlo = reinterpret_cast<const __nv_bfloat16*>(smem + stage * STAGE_BYTES + OFF_BLO);

#pragma unroll
        for (int ks = 0; ks < 2; ks++) {
            const int kb = ks * 16;
            uint32_t a_f[4][4], b_h[4][2], b_l[4][2];
#pragma unroll
            for (int ni = 0; ni < 4; ni++) {
                const __nv_bfloat16* bb = sBhi + (wc * 32 + ni * 8 + tr) * SROW + kb + tc;
                b_h[ni][0] = *reinterpret_cast<const uint32_t*>(bb);
                b_h[ni][1] = *reinterpret_cast<const uint32_t*>(bb + 8);
                const __nv_bfloat16* bl = sBlo + (wc * 32 + ni * 8 + tr) * SROW + kb + tc;
                b_l[ni][0] = *reinterpret_cast<const uint32_t*>(bl);
                b_l[ni][1] = *reinterpret_cast<const uint32_t*>(bl + 8);
            }
#pragma unroll
            for (int mi = 0; mi < 4; mi++) {
                const __nv_bfloat16* ab = sAhi + (wr * 64 + mi * 16 + tr) * SROW + kb + tc;
                a_f[mi][0] = *reinterpret_cast<const uint32_t*>(ab);
                a_f[mi][1] = *reinterpret_cast<const uint32_t*>(ab + 8 * SROW);
                a_f[mi][2] = *reinterpret_cast<const uint32_t*>(ab + 8);
                a_f[mi][3] = *reinterpret_cast<const uint32_t*>(ab + 8 * SROW + 8);
            }
#pragma unroll
            for (int mi = 0; mi < 4; mi++)
#pragma unroll
                for (int ni = 0; ni < 4; ni++) {
                    mma16816(acc[mi][ni], a_f[mi], b_h[ni]);
                    mma16816(acc[mi][ni], a_f[mi], b_l[ni]);
                }
#pragma unroll
            for (int mi = 0; mi < 4; mi++) {
                const __nv_bfloat16* ab = sAlo + (wr * 64 + mi * 16 + tr) * SROW + kb + tc;
                a_f[mi][0] = *reinterpret_cast<const uint32_t*>(ab);
                a_f[mi][1] = *reinterpret_cast<const uint32_t*>(ab + 8 * SROW);
                a_f[mi][2] = *reinterpret_cast<const uint32_t*>(ab + 8);
                a_f[mi][3] = *reinterpret_cast<const uint32_t*>(ab + 8 * SROW + 8);
            }
#pragma unroll
            for (int mi = 0; mi < 4; mi++)
#pragma unroll
                for (int ni = 0; ni < 4; ni++)
                    mma16816(acc[mi][ni], a_f[mi], b_h[ni]);
        }
        __syncthreads();
    }

    const bool isR = (n0 >= Dhalf);
    float* dst = isR ? Rout : Hout;
    const int cbase = (isR ? (n0 - Dhalf) : n0) + wc * 32;
#pragma unroll
    for (int mi = 0; mi < 4; mi++) {
        int r1 = row0 + wr * 64 + mi * 16 + tr;
        int r2 = r1 + 8;
#pragma unroll
        for (int ni = 0; ni < 4; ni++) {
            int cc = cbase + ni * 8 + tc;
            float bx = 0.f, by = 0.f;
            if (isR) { bx = pb[cc]; by = pb[cc + 1]; }
            if (r1 < Nn) {
                float2 o = make_float2(acc[mi][ni][0] + bx, acc[mi][ni][1] + by);
                *reinterpret_cast<float2*>(dst + (size_t)r1 * Dhalf + cc) = o;
            }
            if (r2 < Nn) {
                float2 o = make_float2(acc[mi][ni][2] + bx, acc[mi][ni][3] + by);
                *reinterpret_cast<float2*>(dst + (size_t)r2 * Dhalf + cc) = o;
            }
        }
    }
}

// =========================== scores ===========================
__global__ void k_scores(const float* __restrict__ H, const float* __restrict__ a_s,
                         const float* __restrict__ a_d, int Hh, int C) {
    int idx = blockIdx.x * blockDim.x + threadIdx.x;
    if (idx >= Nn * Hh) return;
    int n = idx / Hh, h = idx - n * Hh;
    int D = Hh * C;
    const float4* hp = reinterpret_cast<const float4*>(H + (size_t)n * D + h * C);
    const float4* sp = reinterpret_cast<const float4*>(a_s + h * C);
    const float4* dp = reinterpret_cast<const float4*>(a_d + h * C);
    float as = 0.f, ad = 0.f;
    for (int c = 0; c < C / 4; c++) {
        float4 v = hp[c], s4 = sp[c], d4 = dp[c];
        as = fmaf(v.x, s4.x, fmaf(v.y, s4.y, fmaf(v.z, s4.z, fmaf(v.w, s4.w, as))));
        ad = fmaf(v.x, d4.x, fmaf(v.y, d4.y, fmaf(v.z, d4.z, fmaf(v.w, d4.w, ad))));
    }
    g_asrc[idx] = as;
    g_adst[idx] = ad;
}

// ============ fused GAT gather + softmax + bias + LN + residual + ELU ============
template<int Hh, int C, bool WB16>
__global__ __launch_bounds__(256) void k_gat(
        const float* __restrict__ H, const float* __restrict__ R,
        const float* __restrict__ bias, const float* __restrict__ gam,
        const float* __restrict__ bet, float* __restrict__ Xout,
        __nv_bfloat16* __restrict__ Ohi, __nv_bfloat16* __restrict__ Olo) {
    constexpr int D = Hh * C;
    constexpr int NF4 = D / 4;
    constexpr int IT = NF4 / 32;
    constexpr int C4 = C / 4;

    int n = blockIdx.x * (blockDim.x >> 5) + (threadIdx.x >> 5);
    if (n >= Nn) return;
    int lane = threadIdx.x & 31;

    float adst_l = (lane < Hh) ? g_adst[n * Hh + lane] : 0.f;
    float denom_l = 0.f;
    float4 acc[IT];
#pragma unroll
    for (int t = 0; t < IT; t++) acc[t] = make_float4(0.f, 0.f, 0.f, 0.f);

    const float4* H4 = reinterpret_cast<const float4*>(H);

    int beg = g_off[n];
    int deg = g_deg[n];
    int s_next = (deg > 0) ? g_srcs[beg] : n;

    for (int e = 0; e <= deg; e++) {
        int s = s_next;
        s_next = (e + 1 < deg) ? g_srcs[beg + e + 1] : n;
        float w_l = 0.f;
        if (lane < Hh) {
            float ev = lrelu(g_asrc[s * Hh + lane] + adst_l);
            w_l = __expf(ev);
            denom_l += w_l;
        }
#pragma unroll
        for (int t = 0; t < IT; t++) {
            int j = lane + t * 32;
            float wj = __shfl_sync(0xFFFFFFFFu, w_l, j / C4);
            float4 hv = H4[(size_t)s * NF4 + j];
            acc[t].x = fmaf(wj, hv.x, acc[t].x);
            acc[t].y = fmaf(wj, hv.y, acc[t].y);
            acc[t].z = fmaf(wj, hv.z, acc[t].z);
            acc[t].w = fmaf(wj, hv.w, acc[t].w);
        }
    }

    float vals[IT * 4];
    float s1 = 0.f, s2 = 0.f;
    const float4* B4 = reinterpret_cast<const float4*>(bias);
#pragma unroll
    for (int t = 0; t < IT; t++) {
        int j = lane + t * 32;
        float dj = __shfl_sync(0xFFFFFFFFu, denom_l, j / C4) + 1e-16f;
        float inv = 1.0f / dj;
        float4 bv = B4[j];
        float4 v = make_float4(fmaf(acc[t].x, inv, bv.x), fmaf(acc[t].y, inv, bv.y),
                               fmaf(acc[t].z, inv, bv.z), fmaf(acc[t].w, inv, bv.w));
        vals[t * 4 + 0] = v.x; vals[t * 4 + 1] = v.y;
        vals[t * 4 + 2] = v.z; vals[t * 4 + 3] = v.w;
        s1 += v.x + v.y + v.z + v.w;
        s2 = fmaf(v.x, v.x, fmaf(v.y, v.y, fmaf(v.z, v.z, fmaf(v.w, v.w, s2))));
    }
#pragma unroll
    for (int o = 16; o > 0; o >>= 1) {
        s1 += __shfl_xor_sync(0xFFFFFFFFu, s1, o);
        s2 += __shfl_xor_sync(0xFFFFFFFFu, s2, o);
    }
    float mean = s1 / (float)D;
    float var = s2 / (float)D - mean * mean;
    float inv = rsqrtf(var + 1e-5f);

    const float4* G4 = reinterpret_cast<const float4*>(gam);
    const float4* E4 = reinterpret_cast<const float4*>(bet);
    const float4* R4 = reinterpret_cast<const float4*>(R);
#pragma unroll
    for (int t = 0; t < IT; t++) {
        int j = lane + t * 32;
        float4 gv = G4[j], ev = E4[j], rv = R4[(size_t)n * NF4 + j];
        float x0 = (vals[t * 4 + 0] - mean) * inv * gv.x + ev.x + rv.x;
        float x1 = (vals[t * 4 + 1] - mean) * inv * gv.y + ev.y + rv.y;
        float x2 = (vals[t * 4 + 2] - mean) * inv * gv.z + ev.z + rv.z;
        float x3 = (vals[t * 4 + 3] - mean) * inv * gv.w + ev.w + rv.w;
        float4 o;
        o.x = x0 > 0.f ? x0 : expm1f(x0);
        o.y = x1 > 0.f ? x1 : expm1f(x1);
        o.z = x2 > 0.f ? x2 : expm1f(x2);
        o.w = x3 > 0.f ? x3 : expm1f(x3);
        if (WB16) {
            __nv_bfloat16 h0 = __float2bfloat16(o.x), h1 = __float2bfloat16(o.y);
            __nv_bfloat16 h2 = __float2bfloat16(o.z), h3 = __float2bfloat16(o.w);
            __nv_bfloat16 l0 = __float2bfloat16(o.x - __bfloat162float(h0));
            __nv_bfloat16 l1 = __float2bfloat16(o.y - __bfloat162float(h1));
            __nv_bfloat16 l2 = __float2bfloat16(o.z - __bfloat162float(h2));
            __nv_bfloat16 l3 = __float2bfloat16(o.w - __bfloat162float(h3));
            __nv_bfloat162* OH = reinterpret_cast<__nv_bfloat162*>(Ohi + (size_t)n * D + j * 4);
            __nv_bfloat162* OL = reinterpret_cast<__nv_bfloat162*>(Olo + (size_t)n * D + j * 4);
            OH[0] = __nv_bfloat162(h0, h1);
            OH[1] = __nv_bfloat162(h2, h3);
            OL[0] = __nv_bfloat162(l0, l1);
            OL[1] = __nv_bfloat162(l2, l3);
        } else {
            reinterpret_cast<float4*>(Xout)[(size_t)n * NF4 + j] = o;
        }
    }
}

// =========================== pooling ===========================
__global__ void k_pool_zero(float* __restrict__ out) {
    int idx = blockIdx.x * blockDim.x + threadIdx.x;
    if (idx < Gg * 128) out[idx] = 0.f;
    if (idx < Gg) g_cnt[idx] = 0.f;
}
__global__ void k_pool(const int* __restrict__ batch, float* __restrict__ out) {
    int idx = blockIdx.x * blockDim.x + threadIdx.x;
    if (idx >= Nn * 32) return;
    int n = idx >> 5, j = idx & 31;
    int b = batch[n];
    float4 v = reinterpret_cast<const float4*>(g_X3)[n * 32 + j];
    red4(&out[b * 128 + j * 4], v);
    if (j == 0) atomicAdd(&g_cnt[b], 1.0f);
}
__global__ void k_pool_div(float* __restrict__ out) {
    int idx = blockIdx.x * blockDim.x + threadIdx.x;
    if (idx >= Gg * 128) return;
    out[idx] /= fmaxf(g_cnt[idx >> 7], 1.0f);
}

// =========================== host ===========================
extern "C" void kernel_launch(void* const* d_in, const int* in_sizes, int n_in,
                              void* d_out, int out_size) {
    const float* x   = (const float*)d_in[0];
    const int* ei    = (const int*)d_in[1];
    const int* batch = (const int*)d_in[2];
    const float* W1 = (const float*)d_in[3],  *as1 = (const float*)d_in[4],
               *ad1 = (const float*)d_in[5],  *b1  = (const float*)d_in[6],
               *g1  = (const float*)d_in[7],  *be1 = (const float*)d_in[8],
               *pw1 = (const float*)d_in[9],  *pb1 = (const float*)d_in[10];
    const float* W2 = (const float*)d_in[11], *as2 = (const float*)d_in[12],
               *ad2 = (const float*)d_in[13], *b2  = (const float*)d_in[14],
               *g2  = (const float*)d_in[15], *be2 = (const float*)d_in[16],
               *pw2 = (const float*)d_in[17], *pb2 = (const float*)d_in[18];
    const float* W3 = (const float*)d_in[19], *as3 = (const float*)d_in[20],
               *ad3 = (const float*)d_in[21], *b3  = (const float*)d_in[22],
               *g3  = (const float*)d_in[23], *be3 = (const float*)d_in[24],
               *pw3 = (const float*)d_in[25], *pb3 = (const float*)d_in[26];
    float* out = (float*)d_out;

    void *pH_, *pR_, *pX3_, *pAhi_, *pAlo_, *pBhi_, *pBlo_;
    cudaGetSymbolAddress(&pH_,  g_H);
    cudaGetSymbolAddress(&pR_,  g_R);
    cudaGetSymbolAddress(&pX3_, g_X3);
    cudaGetSymbolAddress(&pAhi_, g_Ahi);
    cudaGetSymbolAddress(&pAlo_, g_Alo);
    cudaGetSymbolAddress(&pBhi_, g_Bhi);
    cudaGetSymbolAddress(&pBlo_, g_Blo);
    float* pH  = (float*)pH_;
    float* pR  = (float*)pR_;
    float* pX3 = (float*)pX3_;
    __nv_bfloat16* pAhi = (__nv_bfloat16*)pAhi_;
    __nv_bfloat16* pAlo = (__nv_bfloat16*)pAlo_;
    __nv_bfloat16* pBhi = (__nv_bfloat16*)pBhi_;
    __nv_bfloat16* pBlo = (__nv_bfloat16*)pBlo_;

    cudaFuncSetAttribute(k_hgemm, cudaFuncAttributeMaxDynamicSharedMemorySize, 2 * STAGE_BYTES);

    // side stream + events (host-side objects only; created once)
    static cudaStream_t s2 = nullptr;
    static cudaEvent_t evFork = nullptr, evSide = nullptr;
    if (!s2) {
        cudaStreamCreateWithFlags(&s2, cudaStreamNonBlocking);
        cudaEventCreateWithFlags(&evFork, cudaEventDisableTiming);
        cudaEventCreateWithFlags(&evSide, cudaEventDisableTiming);
    }

    const int TB = 256;
    const int MT = (Nn + 127) / 128;   // 391 M-tiles

    // ---- fork: side stream does CSR build + prepack L2/L3 + pool zero ----
    cudaEventRecord(evFork, 0);
    cudaStreamWaitEvent(s2, evFork, 0);

    k_zero_deg<<<(Nn + TB - 1) / TB, TB, 0, s2>>>();
    k_hist<<<(Ee + TB - 1) / TB, TB, 0, s2>>>(ei);
    k_scan1<<<NSCAN_BLK, 256, 0, s2>>>();
    k_scan2<<<1, 256, 0, s2>>>();
    k_scan3<<<(Nn + TB - 1) / TB, TB, 0, s2>>>();
    k_scatter<<<(Ee + TB - 1) / TB, TB, 0, s2>>>(ei);
    k_prepack<<<(2 * 128 * 256 + TB - 1) / TB, TB, 0, s2>>>(W2, pw2, 256, 128, BOFF2);
    k_prepack<<<(2 * 128 * 128 + TB - 1) / TB, TB, 0, s2>>>(W3, pw3, 128, 128, BOFF3);
    k_pool_zero<<<(Gg * 128 + TB - 1) / TB, TB, 0, s2>>>(out);
    cudaEventRecord(evSide, s2);

    // ---- main stream: layer-1 GEMM path ----
    k_cvt<<<(Nn * 128 / 4 + TB - 1) / TB, TB>>>(x, pAhi, pAlo, Nn * 128 / 4);
    k_prepack<<<(2 * 256 * 128 + TB - 1) / TB, TB>>>(W1, pw1, 128, 256, BOFF1);
    k_hgemm<<<dim3(4, MT), 256, 2 * STAGE_BYTES>>>(pAhi, pAlo, pBhi + BOFF1, pBlo + BOFF1,
                                                   pb1, pH, pR, 128, 256);
    k_scores<<<(Nn * 8 + TB - 1) / TB, TB>>>(pH, as1, ad1, 8, 32);

    // join: need CSR (+prepack2/3 later) before gather
    cudaStreamWaitEvent(0, evSide, 0);

    k_gat<8, 32, true><<<(Nn * 32 + TB - 1) / TB, TB>>>(pH, pR, b1, g1, be1, nullptr, pAhi, pAlo);

    // ---- Layer 2: 256 -> 4x32 (D=128) ----
    k_hgemm<<<dim3(2, MT), 256, 2 * STAGE_BYTES>>>(pAhi, pAlo, pBhi + BOFF2, pBlo + BOFF2,
                                                   pb2, pH, pR, 256, 128);
    k_scores<<<(Nn * 4 + TB - 1) / TB, TB>>>(pH, as2, ad2, 4, 32);
    k_gat<4, 32, true><<<(Nn * 32 + TB - 1) / TB, TB>>>(pH, pR, b2, g2, be2, nullptr, pAhi, pAlo);

    // ---- Layer 3: 128 -> 1x128 (D=128) ----
    k_hgemm<<<dim3(2, MT), 256, 2 * STAGE_BYTES>>>(pAhi, pAlo, pBhi + BOFF3, pBlo + BOFF3,
                                                   pb3, pH, pR, 128, 128);
    k_scores<<<(Nn * 1 + TB - 1) / TB, TB>>>(pH, as3, ad3, 1, 128);
    k_gat<1, 128, false><<<(Nn * 32 + TB - 1) / TB, TB>>>(pH, pR, b3, g3, be3, pX3, nullptr, nullptr);

    // ---- pooling ----
    k_pool<<<((size_t)Nn * 32 + TB - 1) / TB, TB>>>(batch, out);
    k_pool_div<<<(Gg * 128 + TB - 1) / TB, TB>>>(out);
}

// round 7
// speedup vs baseline: 2.8853x; 1.2182x over previous
#include <cuda_runtime.h>
#include <cuda_bf16.h>
#include <math.h>
#include <stdint.h>

#define Nn 50000
#define Ee 800000
#define Gg 512
#define NSCAN_BLK 196          // ceil(50000/256)

// weight pack region offsets (elements)
#define BOFF1 0          // L1: 512 x 128
#define BOFF2 65536      // L2: 256 x 256
#define BOFF3 131072     // L3: 256 x 128
#define BTOT  163840

// ---------------- scratch ----------------
__device__ __align__(256) float g_H[Nn * 256];
__device__ __align__(256) float g_R[Nn * 256];
__device__ __align__(256) float g_asrc[Nn * 8];
__device__ __align__(256) float g_adst[Nn * 8];
__device__ __align__(256) float g_cnt[Gg];
// bf16 hi/lo split buffers
__device__ __align__(256) __nv_bfloat16 g_Ahi[Nn * 256];
__device__ __align__(256) __nv_bfloat16 g_Alo[Nn * 256];
__device__ __align__(256) __nv_bfloat16 g_Bhi[BTOT];
__device__ __align__(256) __nv_bfloat16 g_Blo[BTOT];
// CSR
__device__ int g_deg[Nn];
__device__ int g_off[Nn];
__device__ int g_cur[Nn];
__device__ int g_srcs[Ee];
__device__ int g_bsum[256];

__device__ __forceinline__ float lrelu(float x) { return x > 0.0f ? x : 0.2f * x; }
__device__ __forceinline__ void red4(float* p, float4 v) {
    atomicAdd(reinterpret_cast<float4*>(p), v);
}

// =========================== CSR build ===========================
__global__ void k_zero_deg() {
    int i = blockIdx.x * blockDim.x + threadIdx.x;
    if (i < Nn) g_deg[i] = 0;
}
__global__ void k_hist(const int* __restrict__ ei) {
    int e = blockIdx.x * blockDim.x + threadIdx.x;
    if (e < Ee) atomicAdd(&g_deg[ei[Ee + e]], 1);
}
__global__ void k_scan1() {
    __shared__ int sh[256];
    int tid = threadIdx.x;
    int i = blockIdx.x * 256 + tid;
    int v = (i < Nn) ? g_deg[i] : 0;
    sh[tid] = v; __syncthreads();
    for (int off = 1; off < 256; off <<= 1) {
        int t = (tid >= off) ? sh[tid - off] : 0;
        __syncthreads();
        sh[tid] += t;
        __syncthreads();
    }
    if (i < Nn) g_off[i] = sh[tid] - v;
    if (tid == 255) g_bsum[blockIdx.x] = sh[255];
}
__global__ void k_scan2() {
    __shared__ int sh[256];
    int tid = threadIdx.x;
    int v = (tid < NSCAN_BLK) ? g_bsum[tid] : 0;
    sh[tid] = v; __syncthreads();
    for (int off = 1; off < 256; off <<= 1) {
        int t = (tid >= off) ? sh[tid - off] : 0;
        __syncthreads();
        sh[tid] += t;
        __syncthreads();
    }
    if (tid < NSCAN_BLK) g_bsum[tid] = sh[tid] - v;
}
__global__ void k_scan3() {
    int i = blockIdx.x * blockDim.x + threadIdx.x;
    if (i < Nn) {
        g_off[i] += g_bsum[i >> 8];
        g_cur[i] = 0;
    }
}
__global__ void k_scatter(const int* __restrict__ ei) {
    int e = blockIdx.x * blockDim.x + threadIdx.x;
    if (e >= Ee) return;
    int d = ei[Ee + e];
    int pos = g_off[d] + atomicAdd(&g_cur[d], 1);
    g_srcs[pos] = ei[e];
}

// =========================== fp32 -> bf16 hi/lo split (layer-1 input only) ===========================
__global__ void k_cvt(const float* __restrict__ X, __nv_bfloat16* __restrict__ hi,
                      __nv_bfloat16* __restrict__ lo, int total4) {
    int i = blockIdx.x * blockDim.x + threadIdx.x;
    if (i >= total4) return;
    float4 v = reinterpret_cast<const float4*>(X)[i];
    __nv_bfloat16 h0 = __float2bfloat16(v.x), h1 = __float2bfloat16(v.y);
    __nv_bfloat16 h2 = __float2bfloat16(v.z), h3 = __float2bfloat16(v.w);
    __nv_bfloat16 l0 = __float2bfloat16(v.x - __bfloat162float(h0));
    __nv_bfloat16 l1 = __float2bfloat16(v.y - __bfloat162float(h1));
    __nv_bfloat16 l2 = __float2bfloat16(v.z - __bfloat162float(h2));
    __nv_bfloat16 l3 = __float2bfloat16(v.w - __bfloat162float(h3));
    __nv_bfloat162* H2 = reinterpret_cast<__nv_bfloat162*>(hi);
    __nv_bfloat162* L2 = reinterpret_cast<__nv_bfloat162*>(lo);
    H2[i * 2]     = __nv_bfloat162(h0, h1);
    H2[i * 2 + 1] = __nv_bfloat162(h2, h3);
    L2[i * 2]     = __nv_bfloat162(l0, l1);
    L2[i * 2 + 1] = __nv_bfloat162(l2, l3);
}

// weights: Bt[n][k] = (n<Dhalf ? W[k][n] : pw[k][n-Dhalf]), split hi/lo, into region at `boff`
__global__ void k_prepack(const float* __restrict__ W, const float* __restrict__ pw,
                          int K, int Dhalf, int boff) {
    int idx = blockIdx.x * blockDim.x + threadIdx.x;
    int Ncat = 2 * Dhalf;
    if (idx >= Ncat * K) return;
    int n = idx / K, k = idx - n * K;
    float w = (n < Dhalf) ? W[(size_t)k * Dhalf + n] : pw[(size_t)k * Dhalf + (n - Dhalf)];
    __nv_bfloat16 h = __float2bfloat16(w);
    g_Bhi[boff + idx] = h;
    g_Blo[boff + idx] = __float2bfloat16(w - __bfloat162float(h));
}

// =========================== HMMA GEMM (cp.async double-buffered) ===========================
// Fused per-head score epilogue for C=32 layers (Hh>0): each warp's 32-col slice
// is one head; scores computed from accumulator registers + quad shfl reduce.
#define SROW 40
#define STAGE_BYTES 40960
#define OFF_AHI 0
#define OFF_ALO 10240
#define OFF_BHI 20480
#define OFF_BLO 30720

__device__ __forceinline__ void mma16816(float* d, const uint32_t* a, const uint32_t* b) {
    asm volatile(
        "mma.sync.aligned.m16n8k16.row.col.f32.bf16.bf16.f32 "
        "{%0,%1,%2,%3}, {%4,%5,%6,%7}, {%8,%9}, {%0,%1,%2,%3};"
        : "+f"(d[0]), "+f"(d[1]), "+f"(d[2]), "+f"(d[3])
        : "r"(a[0]), "r"(a[1]), "r"(a[2]), "r"(a[3]), "r"(b[0]), "r"(b[1]));
}

__device__ __forceinline__ uint32_t smem_u32(const void* p) {
    uint32_t a;
    asm("{ .reg .u64 t; cvta.to.shared.u64 t, %1; cvt.u32.u64 %0, t; }" : "=r"(a) : "l"(p));
    return a;
}

__device__ __forceinline__ void cp16(uint32_t dst, const void* src, bool ok) {
    asm volatile(
        "{\n\t.reg .pred p;\n\tsetp.ne.u32 p, %2, 0;\n\t"
        "@p cp.async.cg.shared.global [%0], [%1], 16;\n\t"
        "@!p cp.async.cg.shared.global [%0], [%1], 16, 0;\n\t}"
        :: "r"(dst), "l"(src), "r"((unsigned)ok) : "memory");
}

__global__ __launch_bounds__(256) void k_hgemm(
        const __nv_bfloat16* __restrict__ Ahi, const __nv_bfloat16* __restrict__ Alo,
        const __nv_bfloat16* __restrict__ Bhi, const __nv_bfloat16* __restrict__ Blo,
        const float* __restrict__ pb, float* __restrict__ Hout, float* __restrict__ Rout,
        const float* __restrict__ asv, const float* __restrict__ adv,
        int K, int Dhalf, int Hh) {
    extern __shared__ __align__(16) char smem[];
    const uint32_t sbase = smem_u32(smem);

    const int tid = threadIdx.x;
    const int wid = tid >> 5, lane = tid & 31;
    const int row0 = blockIdx.y * 128;
    const int n0 = blockIdx.x * 128;
    const int KC = K >> 5;
    const int wr = wid >> 2;
    const int wc = wid & 3;
    const int tr = lane >> 2;
    const int tc = (lane & 3) * 2;

    const int lr = tid >> 2;
    const int lk = (tid & 3) * 8;

    float acc[4][4][4];
#pragma unroll
    for (int mi = 0; mi < 4; mi++)
#pragma unroll
        for (int ni = 0; ni < 4; ni++)
#pragma unroll
            for (int q = 0; q < 4; q++) acc[mi][ni][q] = 0.f;

    auto load_stage = [&](int stage, int kc) {
        const uint32_t sb = sbase + stage * STAGE_BYTES;
        const int kofs = kc * 32 + lk;
#pragma unroll
        for (int it = 0; it < 2; it++) {
            int r = lr + it * 64;
            uint32_t so = (uint32_t)(r * SROW + lk) * 2;
            int ar = row0 + r;
            bool ok = ar < Nn;
            int arc = ok ? ar : 0;
            cp16(sb + OFF_AHI + so, Ahi + (size_t)arc * K + kofs, ok);
            cp16(sb + OFF_ALO + so, Alo + (size_t)arc * K + kofs, ok);
            cp16(sb + OFF_BHI + so, Bhi + (size_t)(n0 + r) * K + kofs, true);
            cp16(sb + OFF_BLO + so, Blo + (size_t)(n0 + r) * K + kofs, true);
        }
        asm volatile("cp.async.commit_group;" ::: "memory");
    };

    load_stage(0, 0);

    for (int kc = 0; kc < KC; kc++) {
        const int stage = kc & 1;
        if (kc + 1 < KC) {
            load_stage((kc + 1) & 1, kc + 1);
            asm volatile("cp.async.wait_group 1;" ::: "memory");
        } else {
            asm volatile("cp.async.wait_group 0;" ::: "memory");
        }
        __syncthreads();

        const __nv_bfloat16* sAhi = reinterpret_cast<const __nv_bfloat16*>(smem + stage * STAGE_BYTES + OFF_AHI);
        const __nv_bfloat16* sAlo = reinterpret_cast<const __nv_bfloat16*>(smem + stage * STAGE_BYTES + OFF_ALO);
        const __nv_bfloat16* sBhi = reinterpret_cast<const __nv_bfloat16*>(smem + stage * STAGE_BYTES + OFF_BHI);
        const __nv_bfloat16* sBlo = reinterpret_cast<const __nv_bfloat16*>(smem + stage * STAGE_BYTES + OFF_BLO);

#pragma unroll
        for (int ks = 0; ks < 2; ks++) {
            const int kb = ks * 16;
            uint32_t a_f[4][4], b_h[4][2], b_l[4][2];
#pragma unroll
            for (int ni = 0; ni < 4; ni++) {
                const __nv_bfloat16* bb = sBhi + (wc * 32 + ni * 8 + tr) * SROW + kb + tc;
                b_h[ni][0] = *reinterpret_cast<const uint32_t*>(bb);
                b_h[ni][1] = *reinterpret_cast<const uint32_t*>(bb + 8);
                const __nv_bfloat16* bl = sBlo + (wc * 32 + ni * 8 + tr) * SROW + kb + tc;
                b_l[ni][0] = *reinterpret_cast<const uint32_t*>(bl);
                b_l[ni][1] = *reinterpret_cast<const uint32_t*>(bl + 8);
            }
#pragma unroll
            for (int mi = 0; mi < 4; mi++) {
                const __nv_bfloat16* ab = sAhi + (wr * 64 + mi * 16 + tr) * SROW + kb + tc;
                a_f[mi][0] = *reinterpret_cast<const uint32_t*>(ab);
                a_f[mi][1] = *reinterpret_cast<const uint32_t*>(ab + 8 * SROW);
                a_f[mi][2] = *reinterpret_cast<const uint32_t*>(ab + 8);
                a_f[mi][3] = *reinterpret_cast<const uint32_t*>(ab + 8 * SROW + 8);
            }
#pragma unroll
            for (int mi = 0; mi < 4; mi++)
#pragma unroll
                for (int ni = 0; ni < 4; ni++) {
                    mma16816(acc[mi][ni], a_f[mi], b_h[ni]);
                    mma16816(acc[mi][ni], a_f[mi], b_l[ni]);
                }
#pragma unroll
            for (int mi = 0; mi < 4; mi++) {
                const __nv_bfloat16* ab = sAlo + (wr * 64 + mi * 16 + tr) * SROW + kb + tc;
                a_f[mi][0] = *reinterpret_cast<const uint32_t*>(ab);
                a_f[mi][1] = *reinterpret_cast<const uint32_t*>(ab + 8 * SROW);
                a_f[mi][2] = *reinterpret_cast<const uint32_t*>(ab + 8);
                a_f[mi][3] = *reinterpret_cast<const uint32_t*>(ab + 8 * SROW + 8);
            }
#pragma unroll
            for (int mi = 0; mi < 4; mi++)
#pragma unroll
                for (int ni = 0; ni < 4; ni++)
                    mma16816(acc[mi][ni], a_f[mi], b_h[ni]);
        }
        __syncthreads();
    }

    const bool isR = (n0 >= Dhalf);
    float* dst = isR ? Rout : Hout;
    const int cbase = (isR ? (n0 - Dhalf) : n0) + wc * 32;
#pragma unroll
    for (int mi = 0; mi < 4; mi++) {
        int r1 = row0 + wr * 64 + mi * 16 + tr;
        int r2 = r1 + 8;
#pragma unroll
        for (int ni = 0; ni < 4; ni++) {
            int cc = cbase + ni * 8 + tc;
            float bx = 0.f, by = 0.f;
            if (isR) { bx = pb[cc]; by = pb[cc + 1]; }
            if (r1 < Nn) {
                float2 o = make_float2(acc[mi][ni][0] + bx, acc[mi][ni][1] + by);
                *reinterpret_cast<float2*>(dst + (size_t)r1 * Dhalf + cc) = o;
            }
            if (r2 < Nn) {
                float2 o = make_float2(acc[mi][ni][2] + bx, acc[mi][ni][3] + by);
                *reinterpret_cast<float2*>(dst + (size_t)r2 * Dhalf + cc) = o;
            }
        }
    }

    // ---- fused per-head attention scores (C=32 layers only, H CTAs only) ----
    if (Hh > 0 && !isR) {
        const int head = (n0 >> 5) + wc;           // this warp's head
        float as_c[8], ad_c[8];                    // a_src/a_dst slice for cols ni*8+tc(+1)
#pragma unroll
        for (int ni = 0; ni < 4; ni++) {
            int c0 = ni * 8 + tc;
            as_c[ni * 2]     = asv[head * 32 + c0];
            as_c[ni * 2 + 1] = asv[head * 32 + c0 + 1];
            ad_c[ni * 2]     = adv[head * 32 + c0];
            ad_c[ni * 2 + 1] = adv[head * 32 + c0 + 1];
        }
#pragma unroll
        for (int mi = 0; mi < 4; mi++) {
            int r1 = row0 + wr * 64 + mi * 16 + tr;
            int r2 = r1 + 8;
            float as1 = 0.f, ad1 = 0.f, as2 = 0.f, ad2 = 0.f;
#pragma unroll
            for (int ni = 0; ni < 4; ni++) {
                as1 = fmaf(acc[mi][ni][0], as_c[ni * 2], fmaf(acc[mi][ni][1], as_c[ni * 2 + 1], as1));
                ad1 = fmaf(acc[mi][ni][0], ad_c[ni * 2], fmaf(acc[mi][ni][1], ad_c[ni * 2 + 1], ad1));
                as2 = fmaf(acc[mi][ni][2], as_c[ni * 2], fmaf(acc[mi][ni][3], as_c[ni * 2 + 1], as2));
                ad2 = fmaf(acc[mi][ni][2], ad_c[ni * 2], fmaf(acc[mi][ni][3], ad_c[ni * 2 + 1], ad2));
            }
#pragma unroll
            for (int o = 1; o < 4; o <<= 1) {
                as1 += __shfl_xor_sync(0xFFFFFFFFu, as1, o);
                ad1 += __shfl_xor_sync(0xFFFFFFFFu, ad1, o);
                as2 += __shfl_xor_sync(0xFFFFFFFFu, as2, o);
                ad2 += __shfl_xor_sync(0xFFFFFFFFu, ad2, o);
            }
            if ((lane & 3) == 0) {
                if (r1 < Nn) { g_asrc[r1 * Hh + head] = as1; g_adst[r1 * Hh + head] = ad1; }
                if (r2 < Nn) { g_asrc[r2 * Hh + head] = as2; g_adst[r2 * Hh + head] = ad2; }
            }
        }
    }
}

// =========================== scores (layer 3 only, Hh=1, C=128) ===========================
__global__ void k_scores(const float* __restrict__ H, const float* __restrict__ a_s,
                         const float* __restrict__ a_d, int Hh, int C) {
    int idx = blockIdx.x * blockDim.x + threadIdx.x;
    if (idx >= Nn * Hh) return;
    int n = idx / Hh, h = idx - n * Hh;
    int D = Hh * C;
    const float4* hp = reinterpret_cast<const float4*>(H + (size_t)n * D + h * C);
    const float4* sp = reinterpret_cast<const float4*>(a_s + h * C);
    const float4* dp = reinterpret_cast<const float4*>(a_d + h * C);
    float as = 0.f, ad = 0.f;
    for (int c = 0; c < C / 4; c++) {
        float4 v = hp[c], s4 = sp[c], d4 = dp[c];
        as = fmaf(v.x, s4.x, fmaf(v.y, s4.y, fmaf(v.z, s4.z, fmaf(v.w, s4.w, as))));
        ad = fmaf(v.x, d4.x, fmaf(v.y, d4.y, fmaf(v.z, d4.z, fmaf(v.w, d4.w, ad))));
    }
    g_asrc[idx] = as;
    g_adst[idx] = ad;
}

// ============ fused GAT gather + softmax + bias + LN + residual + ELU ============
// WB16: emit next layer's bf16 hi/lo A. POOL: emit directly into pooled output.
template<int Hh, int C, bool WB16, bool POOL>
__global__ __launch_bounds__(256) void k_gat(
        const float* __restrict__ H, const float* __restrict__ R,
        const float* __restrict__ bias, const float* __restrict__ gam,
        const float* __restrict__ bet,
        __nv_bfloat16* __restrict__ Ohi, __nv_bfloat16* __restrict__ Olo,
        const int* __restrict__ batch, float* __restrict__ out) {
    constexpr int D = Hh * C;
    constexpr int NF4 = D / 4;
    constexpr int IT = NF4 / 32;
    constexpr int C4 = C / 4;

    int n = blockIdx.x * (blockDim.x >> 5) + (threadIdx.x >> 5);
    if (n >= Nn) return;
    int lane = threadIdx.x & 31;

    float adst_l = (lane < Hh) ? g_adst[n * Hh + lane] : 0.f;
    float denom_l = 0.f;
    float4 acc[IT];
#pragma unroll
    for (int t = 0; t < IT; t++) acc[t] = make_float4(0.f, 0.f, 0.f, 0.f);

    const float4* H4 = reinterpret_cast<const float4*>(H);

    int beg = g_off[n];
    int deg = g_deg[n];
    int s_next = (deg > 0) ? g_srcs[beg] : n;

    for (int e = 0; e <= deg; e++) {
        int s = s_next;
        s_next = (e + 1 < deg) ? g_srcs[beg + e + 1] : n;
        float w_l = 0.f;
        if (lane < Hh) {
            float ev = lrelu(g_asrc[s * Hh + lane] + adst_l);
            w_l = __expf(ev);
            denom_l += w_l;
        }
#pragma unroll
        for (int t = 0; t < IT; t++) {
            int j = lane + t * 32;
            float wj = __shfl_sync(0xFFFFFFFFu, w_l, j / C4);
            float4 hv = H4[(size_t)s * NF4 + j];
            acc[t].x = fmaf(wj, hv.x, acc[t].x);
            acc[t].y = fmaf(wj, hv.y, acc[t].y);
            acc[t].z = fmaf(wj, hv.z, acc[t].z);
            acc[t].w = fmaf(wj, hv.w, acc[t].w);
        }
    }

    float vals[IT * 4];
    float s1 = 0.f, s2 = 0.f;
    const float4* B4 = reinterpret_cast<const float4*>(bias);
#pragma unroll
    for (int t = 0; t < IT; t++) {
        int j = lane + t * 32;
        float dj = __shfl_sync(0xFFFFFFFFu, denom_l, j / C4) + 1e-16f;
        float inv = 1.0f / dj;
        float4 bv = B4[j];
        float4 v = make_float4(fmaf(acc[t].x, inv, bv.x), fmaf(acc[t].y, inv, bv.y),
                               fmaf(acc[t].z, inv, bv.z), fmaf(acc[t].w, inv, bv.w));
        vals[t * 4 + 0] = v.x; vals[t * 4 + 1] = v.y;
        vals[t * 4 + 2] = v.z; vals[t * 4 + 3] = v.w;
        s1 += v.x + v.y + v.z + v.w;
        s2 = fmaf(v.x, v.x, fmaf(v.y, v.y, fmaf(v.z, v.z, fmaf(v.w, v.w, s2))));
    }
#pragma unroll
    for (int o = 16; o > 0; o >>= 1) {
        s1 += __shfl_xor_sync(0xFFFFFFFFu, s1, o);
        s2 += __shfl_xor_sync(0xFFFFFFFFu, s2, o);
    }
    float mean = s1 / (float)D;
    float var = s2 / (float)D - mean * mean;
    float inv = rsqrtf(var + 1e-5f);

    const float4* G4 = reinterpret_cast<const float4*>(gam);
    const float4* E4 = reinterpret_cast<const float4*>(bet);
    const float4* R4 = reinterpret_cast<const float4*>(R);
#pragma unroll
    for (int t = 0; t < IT; t++) {
        int j = lane + t * 32;
        float4 gv = G4[j], ev = E4[j], rv = R4[(size_t)n * NF4 + j];
        float x0 = (vals[t * 4 + 0] - mean) * inv * gv.x + ev.x + rv.x;
        float x1 = (vals[t * 4 + 1] - mean) * inv * gv.y + ev.y + rv.y;
        float x2 = (vals[t * 4 + 2] - mean) * inv * gv.z + ev.z + rv.z;
        float x3 = (vals[t * 4 + 3] - mean) * inv * gv.w + ev.w + rv.w;
        float4 o;
        o.x = x0 > 0.f ? x0 : expm1f(x0);
        o.y = x1 > 0.f ? x1 : expm1f(x1);
        o.z = x2 > 0.f ? x2 : expm1f(x2);
        o.w = x3 > 0.f ? x3 : expm1f(x3);
        if (WB16) {
            __nv_bfloat16 h0 = __float2bfloat16(o.x), h1 = __float2bfloat16(o.y);
            __nv_bfloat16 h2 = __float2bfloat16(o.z), h3 = __float2bfloat16(o.w);
            __nv_bfloat16 l0 = __float2bfloat16(o.x - __bfloat162float(h0));
            __nv_bfloat16 l1 = __float2bfloat16(o.y - __bfloat162float(h1));
            __nv_bfloat16 l2 = __float2bfloat16(o.z - __bfloat162float(h2));
            __nv_bfloat16 l3 = __float2bfloat16(o.w - __bfloat162float(h3));
            __nv_bfloat162* OH = reinterpret_cast<__nv_bfloat162*>(Ohi + (size_t)n * D + j * 4);
            __nv_bfloat162* OL = reinterpret_cast<__nv_bfloat162*>(Olo + (size_t)n * D + j * 4);
            OH[0] = __nv_bfloat162(h0, h1);
            OH[1] = __nv_bfloat162(h2, h3);
            OL[0] = __nv_bfloat162(l0, l1);
            OL[1] = __nv_bfloat162(l2, l3);
        } else if (POOL) {
            int b = batch[n];
            red4(&out[b * 128 + j * 4], o);
            if (j == 0) atomicAdd(&g_cnt[b], 1.0f);
        }
    }
}

// =========================== pooling finalize ===========================
__global__ void k_pool_zero(float* __restrict__ out) {
    int idx = blockIdx.x * blockDim.x + threadIdx.x;
    if (idx < Gg * 128) out[idx] = 0.f;
    if (idx < Gg) g_cnt[idx] = 0.f;
}
__global__ void k_pool_div(float* __restrict__ out) {
    int idx = blockIdx.x * blockDim.x + threadIdx.x;
    if (idx >= Gg * 128) return;
    out[idx] /= fmaxf(g_cnt[idx >> 7], 1.0f);
}

// =========================== host ===========================
extern "C" void kernel_launch(void* const* d_in, const int* in_sizes, int n_in,
                              void* d_out, int out_size) {
    const float* x   = (const float*)d_in[0];
    const int* ei    = (const int*)d_in[1];
    const int* batch = (const int*)d_in[2];
    const float* W1 = (const float*)d_in[3],  *as1 = (const float*)d_in[4],
               *ad1 = (const float*)d_in[5],  *b1  = (const float*)d_in[6],
               *g1  = (const float*)d_in[7],  *be1 = (const float*)d_in[8],
               *pw1 = (const float*)d_in[9],  *pb1 = (const float*)d_in[10];
    const float* W2 = (const float*)d_in[11], *as2 = (const float*)d_in[12],
               *ad2 = (const float*)d_in[13], *b2  = (const float*)d_in[14],
               *g2  = (const float*)d_in[15], *be2 = (const float*)d_in[16],
               *pw2 = (const float*)d_in[17], *pb2 = (const float*)d_in[18];
    const float* W3 = (const float*)d_in[19], *as3 = (const float*)d_in[20],
               *ad3 = (const float*)d_in[21], *b3  = (const float*)d_in[22],
               *g3  = (const float*)d_in[23], *be3 = (const float*)d_in[24],
               *pw3 = (const float*)d_in[25], *pb3 = (const float*)d_in[26];
    float* out = (float*)d_out;

    void *pH_, *pR_, *pAhi_, *pAlo_, *pBhi_, *pBlo_;
    cudaGetSymbolAddress(&pH_,  g_H);
    cudaGetSymbolAddress(&pR_,  g_R);
    cudaGetSymbolAddress(&pAhi_, g_Ahi);
    cudaGetSymbolAddress(&pAlo_, g_Alo);
    cudaGetSymbolAddress(&pBhi_, g_Bhi);
    cudaGetSymbolAddress(&pBlo_, g_Blo);
    float* pH  = (float*)pH_;
    float* pR  = (float*)pR_;
    __nv_bfloat16* pAhi = (__nv_bfloat16*)pAhi_;
    __nv_bfloat16* pAlo = (__nv_bfloat16*)pAlo_;
    __nv_bfloat16* pBhi = (__nv_bfloat16*)pBhi_;
    __nv_bfloat16* pBlo = (__nv_bfloat16*)pBlo_;

    cudaFuncSetAttribute(k_hgemm, cudaFuncAttributeMaxDynamicSharedMemorySize, 2 * STAGE_BYTES);

    static cudaStream_t s2 = nullptr;
    static cudaEvent_t evFork = nullptr, evSide = nullptr;
    if (!s2) {
        cudaStreamCreateWithFlags(&s2, cudaStreamNonBlocking);
        cudaEventCreateWithFlags(&evFork, cudaEventDisableTiming);
        cudaEventCreateWithFlags(&evSide, cudaEventDisableTiming);
    }

    const int TB = 256;
    const int MT = (Nn + 127) / 128;

    // ---- fork: side stream does CSR build + prepack L2/L3 + pool zero ----
    cudaEventRecord(evFork, 0);
    cudaStreamWaitEvent(s2, evFork, 0);

    k_zero_deg<<<(Nn + TB - 1) / TB, TB, 0, s2>>>();
    k_hist<<<(Ee + TB - 1) / TB, TB, 0, s2>>>(ei);
    k_scan1<<<NSCAN_BLK, 256, 0, s2>>>();
    k_scan2<<<1, 256, 0, s2>>>();
    k_scan3<<<(Nn + TB - 1) / TB, TB, 0, s2>>>();
    k_scatter<<<(Ee + TB - 1) / TB, TB, 0, s2>>>(ei);
    k_prepack<<<(2 * 128 * 256 + TB - 1) / TB, TB, 0, s2>>>(W2, pw2, 256, 128, BOFF2);
    k_prepack<<<(2 * 128 * 128 + TB - 1) / TB, TB, 0, s2>>>(W3, pw3, 128, 128, BOFF3);
    k_pool_zero<<<(Gg * 128 + TB - 1) / TB, TB, 0, s2>>>(out);
    cudaEventRecord(evSide, s2);

    // ---- main stream: layer 1 (scores fused into GEMM epilogue) ----
    k_cvt<<<(Nn * 128 / 4 + TB - 1) / TB, TB>>>(x, pAhi, pAlo, Nn * 128 / 4);
    k_prepack<<<(2 * 256 * 128 + TB - 1) / TB, TB>>>(W1, pw1, 128, 256, BOFF1);
    k_hgemm<<<dim3(4, MT), 256, 2 * STAGE_BYTES>>>(pAhi, pAlo, pBhi + BOFF1, pBlo + BOFF1,
                                                   pb1, pH, pR, as1, ad1, 128, 256, 8);

    cudaStreamWaitEvent(0, evSide, 0);

    k_gat<8, 32, true, false><<<(Nn * 32 + TB - 1) / TB, TB>>>(pH, pR, b1, g1, be1,
                                                               pAhi, pAlo, nullptr, nullptr);

    // ---- Layer 2 (scores fused) ----
    k_hgemm<<<dim3(2, MT), 256, 2 * STAGE_BYTES>>>(pAhi, pAlo, pBhi + BOFF2, pBlo + BOFF2,
                                                   pb2, pH, pR, as2, ad2, 256, 128, 4);
    k_gat<4, 32, true, false><<<(Nn * 32 + TB - 1) / TB, TB>>>(pH, pR, b2, g2, be2,
                                                               pAhi, pAlo, nullptr, nullptr);

    // ---- Layer 3 (standalone scores; pool fused into gat) ----
    k_hgemm<<<dim3(2, MT), 256, 2 * STAGE_BYTES>>>(pAhi, pAlo, pBhi + BOFF3, pBlo + BOFF3,
                                                   pb3, pH, pR, nullptr, nullptr, 128, 128, 0);
    k_scores<<<(Nn + TB - 1) / TB, TB>>>(pH, as3, ad3, 1, 128);
    k_gat<1, 128, false, true><<<(Nn * 32 + TB - 1) / TB, TB>>>(pH, pR, b3, g3, be3,
                                                                nullptr, nullptr, batch, out);

    k_pool_div<<<(Gg * 128 + TB - 1) / TB, TB>>>(out);
}